// round 14
// baseline (speedup 1.0000x reference)
#include <cuda_runtime.h>
#include <cuda_fp16.h>
#include <stdint.h>
#include <math.h>

#define DEV_INLINE __device__ __forceinline__

constexpr int Bsz = 4, Cc = 256, Hh = 128, Ww = 128, Nn = Hh * Ww;
constexpr int HEADS = 8, DHd = 32, Gg = 64, INNERc = 256, HIDc = 1024;
constexpr int Lnum = 4, OUTc = 4;
constexpr int ROWS = Bsz * Nn;  // 65536

// packed-weight layout (u32 = bf16x2 k-pairs, k-major), per layer offsets
constexpr int WPK_CONVX = 0;                       // Kp=1152, N=256
constexpr int WPK_CONVFX = 1152 * 256;
constexpr int WPK_WO = 2 * 1152 * 256;             // Kp=128, N=256
constexpr int WPK_W1 = WPK_WO + 128 * 256;         // Kp=128, N=1024
constexpr int WPK_W2 = WPK_W1 + 128 * 1024;        // Kp=512, N=256
constexpr int WPK_LAYER = WPK_W2 + 512 * 256;

// ---------------- scratch (device globals; no runtime alloc) ----------------
__device__ float g_fx[ROWS * Cc];
__device__ uint32_t g_lnbf[ROWS * (Cc / 2)];
__device__ uint32_t g_xmidh[ROWS * (INNERc / 2)];
__device__ uint32_t g_fxmidh[ROWS * (INNERc / 2)];
__device__ __half g_swh[(size_t)Bsz * HEADS * Nn * Gg];
__device__ float g_st[Bsz * HEADS * Gg * DHd];
__device__ float g_norm[Bsz * HEADS * Gg];
__device__ uint32_t g_otp[Bsz * HEADS * (Gg / 2) * DHd];
__device__ uint32_t g_outxbf[ROWS * (INNERc / 2)];
__device__ uint32_t g_hidbf[ROWS * (HIDc / 2)];
__device__ uint32_t g_wpk[Lnum * WPK_LAYER];

// ---------------- helpers ----------------
DEV_INLINE float warpSum(float v) {
#pragma unroll
    for (int o = 16; o; o >>= 1) v += __shfl_xor_sync(0xffffffffu, v, o);
    return v;
}
DEV_INLINE float warpMax(float v) {
#pragma unroll
    for (int o = 16; o; o >>= 1) v = fmaxf(v, __shfl_xor_sync(0xffffffffu, v, o));
    return v;
}
DEV_INLINE uint32_t packbf(float lo, float hi) {
    uint32_t r;
    asm("cvt.rn.bf16x2.f32 %0, %1, %2;" : "=r"(r) : "f"(hi), "f"(lo));
    return r;
}
DEV_INLINE uint32_t packh(float lo, float hi) {
    uint32_t r;
    asm("cvt.rn.f16x2.f32 %0, %1, %2;" : "=r"(r) : "f"(hi), "f"(lo));
    return r;
}
DEV_INLINE void mma_bf16(float c[4], const uint32_t a[4], const uint32_t b[2]) {
    asm volatile(
        "mma.sync.aligned.m16n8k16.row.col.f32.bf16.bf16.f32 "
        "{%0,%1,%2,%3}, {%4,%5,%6,%7}, {%8,%9}, {%0,%1,%2,%3};"
        : "+f"(c[0]), "+f"(c[1]), "+f"(c[2]), "+f"(c[3])
        : "r"(a[0]), "r"(a[1]), "r"(a[2]), "r"(a[3]), "r"(b[0]), "r"(b[1]));
}
DEV_INLINE void mma_f16(float c[4], const uint32_t a[4], const uint32_t b[2]) {
    asm volatile(
        "mma.sync.aligned.m16n8k16.row.col.f32.f16.f16.f32 "
        "{%0,%1,%2,%3}, {%4,%5,%6,%7}, {%8,%9}, {%0,%1,%2,%3};"
        : "+f"(c[0]), "+f"(c[1]), "+f"(c[2]), "+f"(c[3])
        : "r"(a[0]), "r"(a[1]), "r"(a[2]), "r"(a[3]), "r"(b[0]), "r"(b[1]));
}
DEV_INLINE void ldsm4(uint32_t& r0, uint32_t& r1, uint32_t& r2, uint32_t& r3,
                      uint32_t addr) {
    asm volatile("ldmatrix.sync.aligned.m8n8.x4.shared.b16 {%0,%1,%2,%3}, [%4];"
                 : "=r"(r0), "=r"(r1), "=r"(r2), "=r"(r3)
                 : "r"(addr));
}
DEV_INLINE void ldsm4t(uint32_t& r0, uint32_t& r1, uint32_t& r2, uint32_t& r3,
                       uint32_t addr) {
    asm volatile("ldmatrix.sync.aligned.m8n8.x4.trans.shared.b16 {%0,%1,%2,%3}, [%4];"
                 : "=r"(r0), "=r"(r1), "=r"(r2), "=r"(r3)
                 : "r"(addr));
}

// ---------------- copy input ----------------
__global__ void copy_in_kernel(const float* __restrict__ src) {
    int i = blockIdx.x * 256 + threadIdx.x;
    g_fx[i] = src[i];
}

// ---------------- weight pre-pack: k-major bf16 k-pair packing --------------
__global__ void pack_kernel(const float* __restrict__ src, uint32_t* __restrict__ dst,
                            int Kp, int N, int L, size_t sstride, size_t dstride) {
    int total = L * Kp * N;
    for (int idx = blockIdx.x * blockDim.x + threadIdx.x; idx < total;
         idx += gridDim.x * blockDim.x) {
        int l = idx / (Kp * N);
        int r = idx - l * (Kp * N);
        int kp = r / N, n = r - kp * N;
        float lo = src[l * sstride + (size_t)(2 * kp) * N + n];
        float hi = src[l * sstride + (size_t)(2 * kp + 1) * N + n];
        dst[l * dstride + (size_t)kp * N + n] = packbf(lo, hi);
    }
}

// ---------------- layernorm over C=256, one block per row (proven) ----------
__global__ void ln_kernel(const float* __restrict__ in, uint32_t* __restrict__ outb,
                          const float* __restrict__ w, const float* __restrict__ b) {
    int row = blockIdx.x;
    int t = threadIdx.x;
    float v = in[row * Cc + t];
    __shared__ float red[8];
    __shared__ float s_mean, s_rstd;
    float s = warpSum(v);
    if ((t & 31) == 0) red[t >> 5] = s;
    __syncthreads();
    if (t < 8) {
        float x = red[t];
#pragma unroll
        for (int o = 4; o; o >>= 1) x += __shfl_xor_sync(0xffu, x, o);
        if (t == 0) s_mean = x * (1.f / Cc);
    }
    __syncthreads();
    float m = s_mean;
    float d = v - m;
    float s2 = warpSum(d * d);
    if ((t & 31) == 0) red[t >> 5] = s2;
    __syncthreads();
    if (t < 8) {
        float x = red[t];
#pragma unroll
        for (int o = 4; o; o >>= 1) x += __shfl_xor_sync(0xffu, x, o);
        if (t == 0) s_rstd = rsqrtf(x * (1.f / Cc) + 1e-5f);
    }
    __syncthreads();
    float o = d * s_rstd * w[t] + b[t];
    float nb = __shfl_xor_sync(0xffffffffu, o, 1);
    if (!(t & 1)) outb[row * (Cc / 2) + (t >> 1)] = packbf(o, nb);
}

// ---------------- fused ln3 + head: out = ln(fx)@w_out + b_out --------------
__global__ void ln_head_kernel(const float* __restrict__ in, const float* __restrict__ lw,
                               const float* __restrict__ lb, const float* __restrict__ wout,
                               const float* __restrict__ bout, float* __restrict__ out) {
    int warp = threadIdx.x >> 5, lane = threadIdx.x & 31;
    int row = blockIdx.x * 8 + warp;
    int c0 = lane * 8;
    const float* rp = in + (size_t)row * Cc + c0;
    float v[8];
    *(float4*)(v) = *(const float4*)rp;
    *(float4*)(v + 4) = *(const float4*)(rp + 4);
    float s = v[0] + v[1] + v[2] + v[3] + v[4] + v[5] + v[6] + v[7];
    float m = warpSum(s) * (1.f / Cc);
    float s2 = 0.f;
#pragma unroll
    for (int j = 0; j < 8; j++) {
        v[j] -= m;
        s2 += v[j] * v[j];
    }
    float rstd = rsqrtf(warpSum(s2) * (1.f / Cc) + 1e-5f);
    float wv[8], bv[8];
    *(float4*)(wv) = *(const float4*)(lw + c0);
    *(float4*)(wv + 4) = *(const float4*)(lw + c0 + 4);
    *(float4*)(bv) = *(const float4*)(lb + c0);
    *(float4*)(bv + 4) = *(const float4*)(lb + c0 + 4);
    float o[8];
#pragma unroll
    for (int j = 0; j < 8; j++) o[j] = v[j] * rstd * wv[j] + bv[j];
    float p[4] = {0.f, 0.f, 0.f, 0.f};
#pragma unroll
    for (int j = 0; j < 8; j++) {
        float4 wr = *(const float4*)&wout[(c0 + j) * 4];
        p[0] += o[j] * wr.x;
        p[1] += o[j] * wr.y;
        p[2] += o[j] * wr.z;
        p[3] += o[j] * wr.w;
    }
#pragma unroll
    for (int oc = 0; oc < 4; oc++) p[oc] = warpSum(p[oc]);
    if (lane == 0) {
        float4 bo4 = *(const float4*)bout;
        *(float4*)&out[(size_t)row * 4] =
            make_float4(p[0] + bo4.x, p[1] + bo4.y, p[2] + bo4.z, p[3] + bo4.w);
    }
}

// ===== bf16 GEMM (R8): dbl-buffered smem, register-staged LDG, 1 sync/chunk ==
constexpr int ABUF = 128 * 20;  // u32 per A stage

template <bool GELU, bool RES, bool BFOUT>
__global__ __launch_bounds__(256, 2)
void gemm_bf16_kernel(const uint32_t* __restrict__ A, const uint32_t* __restrict__ Bw,
                      const float* __restrict__ bias, const float* __restrict__ resid,
                      float* __restrict__ CoutF, uint32_t* __restrict__ CoutB,
                      int Kp, int Nc) {
    __shared__ uint32_t As2[2][128][20];
    __shared__ uint32_t Bs2[2][16][136];
    int tid = threadIdx.x;
    int m0 = blockIdx.x * 128, nc0 = blockIdx.y * 128;
    int wid = tid >> 5, lane = tid & 31;
    int wm = (wid >> 2) * 64, wn = (wid & 3) * 32;
    int gid = lane >> 2, tig = lane & 3;

    uint32_t smemA = (uint32_t)__cvta_generic_to_shared(&As2[0][0][0]);
    int arow = wm + (lane & 7) + ((lane >> 3) & 1) * 8;
    uint32_t aBase = smemA + (uint32_t)((arow * 20 + ((lane >> 4) << 2)) * 4);

    float acc[4][4][4];
#pragma unroll
    for (int mi = 0; mi < 4; mi++)
#pragma unroll
        for (int ni = 0; ni < 4; ni++)
#pragma unroll
            for (int q = 0; q < 4; q++) acc[mi][ni][q] = 0.f;

    uint4 aP[2], bP[2];
#pragma unroll
    for (int j = 0; j < 2; j++) {
        int s = tid + 256 * j;
        aP[j] = *(const uint4*)&A[(size_t)(m0 + (s >> 2)) * Kp + (s & 3) * 4];
        bP[j] = *(const uint4*)&Bw[(size_t)(s >> 5) * Nc + nc0 + (s & 31) * 4];
    }
#pragma unroll
    for (int j = 0; j < 2; j++) {
        int s = tid + 256 * j;
        *(uint4*)&As2[0][s >> 2][(s & 3) * 4] = aP[j];
        *(uint4*)&Bs2[0][s >> 5][(s & 31) * 4] = bP[j];
    }
    __syncthreads();

    int nch = Kp >> 4;
    for (int ch = 0; ch < nch; ch++) {
        int cur = ch & 1;
        if (ch + 1 < nch) {
            int kc = (ch + 1) * 16;
#pragma unroll
            for (int j = 0; j < 2; j++) {
                int s = tid + 256 * j;
                aP[j] = *(const uint4*)&A[(size_t)(m0 + (s >> 2)) * Kp + kc + (s & 3) * 4];
                bP[j] = *(const uint4*)&Bw[(size_t)(kc + (s >> 5)) * Nc + nc0 + (s & 31) * 4];
            }
        }
        uint32_t aB = aBase + cur * (ABUF * 4);
#pragma unroll
        for (int ks = 0; ks < 2; ks++) {
            int kpb = ks * 8;
            uint32_t bf[4][2];
#pragma unroll
            for (int ni = 0; ni < 4; ni++) {
                int n = wn + ni * 8 + gid;
                bf[ni][0] = Bs2[cur][kpb + tig][n];
                bf[ni][1] = Bs2[cur][kpb + tig + 4][n];
            }
#pragma unroll
            for (int mi = 0; mi < 4; mi++) {
                uint32_t a[4];
                ldsm4(a[0], a[1], a[2], a[3], aB + mi * 1280 + ks * 32);
#pragma unroll
                for (int ni = 0; ni < 4; ni++) mma_bf16(acc[mi][ni], a, bf[ni]);
            }
        }
        if (ch + 1 < nch) {
            int nxt = cur ^ 1;
#pragma unroll
            for (int j = 0; j < 2; j++) {
                int s = tid + 256 * j;
                *(uint4*)&As2[nxt][s >> 2][(s & 3) * 4] = aP[j];
                *(uint4*)&Bs2[nxt][s >> 5][(s & 31) * 4] = bP[j];
            }
            __syncthreads();
        }
    }
#pragma unroll
    for (int mi = 0; mi < 4; mi++) {
        int r = m0 + wm + mi * 16 + gid;
#pragma unroll
        for (int ni = 0; ni < 4; ni++) {
            int cb = nc0 + wn + ni * 8 + tig * 2;
            float b0 = bias[cb], b1 = bias[cb + 1];
            float v0 = acc[mi][ni][0] + b0, v1 = acc[mi][ni][1] + b1;
            float v2 = acc[mi][ni][2] + b0, v3 = acc[mi][ni][3] + b1;
            if (GELU) {
                v0 = 0.5f * v0 * (1.f + erff(v0 * 0.70710678118654752f));
                v1 = 0.5f * v1 * (1.f + erff(v1 * 0.70710678118654752f));
                v2 = 0.5f * v2 * (1.f + erff(v2 * 0.70710678118654752f));
                v3 = 0.5f * v3 * (1.f + erff(v3 * 0.70710678118654752f));
            }
            if (RES) {
                v0 += resid[(size_t)r * Nc + cb];
                v1 += resid[(size_t)r * Nc + cb + 1];
                v2 += resid[(size_t)(r + 8) * Nc + cb];
                v3 += resid[(size_t)(r + 8) * Nc + cb + 1];
            }
            if (BFOUT) {
                CoutB[(size_t)r * (Nc / 2) + (cb >> 1)] = packbf(v0, v1);
                CoutB[(size_t)(r + 8) * (Nc / 2) + (cb >> 1)] = packbf(v2, v3);
            } else {
                *(float2*)&CoutF[(size_t)r * Nc + cb] = make_float2(v0, v1);
                *(float2*)&CoutF[(size_t)(r + 8) * Nc + cb] = make_float2(v2, v3);
            }
        }
    }
}

// ===== bf16 conv 3x3 implicit GEMM (R8): dbl-buffered, 72 chunks ============
__global__ __launch_bounds__(256, 2)
void conv_bf16_kernel(const uint32_t* __restrict__ Abf, const uint32_t* __restrict__ Wp,
                      const float* __restrict__ bias, uint32_t* __restrict__ CoutH) {
    __shared__ uint32_t As2[2][128][20];
    __shared__ uint32_t Bs2[2][16][136];
    int tid = threadIdx.x;
    int m0 = blockIdx.x * 128, nc0 = blockIdx.y * 128;
    int b = blockIdx.x >> 7;
    int y = blockIdx.x & 127;
    int wid = tid >> 5, lane = tid & 31;
    int wm = (wid >> 2) * 64, wn = (wid & 3) * 32;
    int gid = lane >> 2, tig = lane & 3;

    uint32_t smemA = (uint32_t)__cvta_generic_to_shared(&As2[0][0][0]);
    int arow = wm + (lane & 7) + ((lane >> 3) & 1) * 8;
    uint32_t aBase = smemA + (uint32_t)((arow * 20 + ((lane >> 4) << 2)) * 4);

    float acc[4][4][4];
#pragma unroll
    for (int mi = 0; mi < 4; mi++)
#pragma unroll
        for (int ni = 0; ni < 4; ni++)
#pragma unroll
            for (int q = 0; q < 4; q++) acc[mi][ni][q] = 0.f;

    uint4 aP[2], bP[2];
    const uint4 z4 = make_uint4(0, 0, 0, 0);
    {
        int yy = y - 1;
#pragma unroll
        for (int j = 0; j < 2; j++) {
            int s = tid + 256 * j;
            int xx = (s >> 2) - 1;
            aP[j] = ((unsigned)yy < 128u && (unsigned)xx < 128u)
                        ? *(const uint4*)&Abf[(size_t)(((b << 7) + yy) * 128 + xx) * 128 +
                                              (s & 3) * 4]
                        : z4;
            bP[j] = *(const uint4*)&Wp[(size_t)(s >> 5) * 256 + nc0 + (s & 31) * 4];
        }
    }
#pragma unroll
    for (int j = 0; j < 2; j++) {
        int s = tid + 256 * j;
        *(uint4*)&As2[0][s >> 2][(s & 3) * 4] = aP[j];
        *(uint4*)&Bs2[0][s >> 5][(s & 31) * 4] = bP[j];
    }
    __syncthreads();

    for (int ch = 0; ch < 72; ch++) {
        int cur = ch & 1;
        if (ch + 1 < 72) {
            int cn = ch + 1;
            int tap = cn >> 3, icp0 = (cn & 7) * 16;
            int dy = tap / 3 - 1, dx = tap % 3 - 1;
            int yy = y + dy;
#pragma unroll
            for (int j = 0; j < 2; j++) {
                int s = tid + 256 * j;
                int xx = (s >> 2) + dx;
                aP[j] = ((unsigned)yy < 128u && (unsigned)xx < 128u)
                            ? *(const uint4*)&Abf[(size_t)(((b << 7) + yy) * 128 + xx) * 128 +
                                                  icp0 + (s & 3) * 4]
                            : z4;
                bP[j] = *(const uint4*)&Wp[(size_t)(tap * 128 + icp0 + (s >> 5)) * 256 + nc0 +
                                           (s & 31) * 4];
            }
        }
        uint32_t aB = aBase + cur * (ABUF * 4);
#pragma unroll
        for (int ks = 0; ks < 2; ks++) {
            int kpb = ks * 8;
            uint32_t bf[4][2];
#pragma unroll
            for (int ni = 0; ni < 4; ni++) {
                int n = wn + ni * 8 + gid;
                bf[ni][0] = Bs2[cur][kpb + tig][n];
                bf[ni][1] = Bs2[cur][kpb + tig + 4][n];
            }
#pragma unroll
            for (int mi = 0; mi < 4; mi++) {
                uint32_t a[4];
                ldsm4(a[0], a[1], a[2], a[3], aB + mi * 1280 + ks * 32);
#pragma unroll
                for (int ni = 0; ni < 4; ni++) mma_bf16(acc[mi][ni], a, bf[ni]);
            }
        }
        if (ch + 1 < 72) {
            int nxt = cur ^ 1;
#pragma unroll
            for (int j = 0; j < 2; j++) {
                int s = tid + 256 * j;
                *(uint4*)&As2[nxt][s >> 2][(s & 3) * 4] = aP[j];
                *(uint4*)&Bs2[nxt][s >> 5][(s & 31) * 4] = bP[j];
            }
            __syncthreads();
        }
    }
#pragma unroll
    for (int mi = 0; mi < 4; mi++) {
        int r = m0 + wm + mi * 16 + gid;
#pragma unroll
        for (int ni = 0; ni < 4; ni++) {
            int cb = nc0 + wn + ni * 8 + tig * 2;
            float b0 = bias[cb], b1 = bias[cb + 1];
            CoutH[(size_t)r * 128 + (cb >> 1)] = packh(acc[mi][ni][0] + b0, acc[mi][ni][1] + b1);
            CoutH[(size_t)(r + 8) * 128 + (cb >> 1)] =
                packh(acc[mi][ni][2] + b0, acc[mi][ni][3] + b1);
        }
    }
}

// ---------------- slice logits + softmax over G=64 ----------------
__global__ void slice_softmax_kernel(const uint32_t* __restrict__ xmidh,
                                     const float* __restrict__ sw_w,
                                     const float* __restrict__ sw_b,
                                     const float* __restrict__ temp) {
    int row = blockIdx.x;
    int b = row >> 14;
    int n = row & (Nn - 1);
    int tid = threadIdx.x;  // 512
    __shared__ float sx[256];
    __shared__ float wred[16];
    if (tid < 128) {
        __half2 v = *(const __half2*)&xmidh[(size_t)row * 128 + tid];
        sx[2 * tid] = __low2float(v);
        sx[2 * tid + 1] = __high2float(v);
    }
    __syncthreads();
    int h = tid >> 6, g = tid & 63;
    const float* xh = sx + h * 32;
    float acc = sw_b[g];
#pragma unroll
    for (int d = 0; d < 32; d++) acc += xh[d] * sw_w[d * 64 + g];
    float tp = fminf(fmaxf(temp[h], 0.1f), 5.0f);
    acc /= tp;
    int wid = tid >> 5, lane = tid & 31;
    float m = warpMax(acc);
    if (lane == 0) wred[wid] = m;
    __syncthreads();
    m = fmaxf(wred[h * 2], wred[h * 2 + 1]);
    float e = expf(acc - m);
    __syncthreads();
    float s = warpSum(e);
    if (lane == 0) wred[wid] = s;
    __syncthreads();
    s = wred[h * 2] + wred[h * 2 + 1];
    g_swh[((size_t)(b * HEADS + h) * Nn + n) * Gg + g] = __float2half(e / s);
}

__global__ void zero_stats_kernel() {
    int i = blockIdx.x * 256 + threadIdx.x;
    if (i < Bsz * HEADS * Gg * DHd) g_st[i] = 0.f;
    if (i < Bsz * HEADS * Gg) g_norm[i] = 0.f;
}

// ===== st via fp16 mma: st[64g][32d] += sw^T @ fxmid ; norm[g] += col-sum ====
__global__ __launch_bounds__(256)
void st_mma_kernel() {
    __shared__ uint32_t Ssw[128][36];
    __shared__ uint32_t Sfm[128][20];
    int bh = blockIdx.x;
    int split = blockIdx.y;
    int b = bh >> 3, h = bh & 7;
    int tid = threadIdx.x;
    int wid = tid >> 5, lane = tid & 31;
    int gseg = (wid & 3) * 16;
    int kseg = (wid >> 2) * 64;

    const uint32_t* swp = (const uint32_t*)g_swh + ((size_t)bh * Nn + split * 1024) * 32;
    const uint32_t* fm = g_fxmidh + (size_t)(b * Nn + split * 1024) * 128 + h * 16;

    uint32_t swB = (uint32_t)__cvta_generic_to_shared(&Ssw[0][0]);
    uint32_t fmB = (uint32_t)__cvta_generic_to_shared(&Sfm[0][0]);
    int aRow = ((lane >> 4) & 1) * 8 + (lane & 7);
    uint32_t aOff = swB + (uint32_t)(((gseg + ((lane >> 3) & 1) * 8) >> 1) * 4);
    int bRow = ((lane >> 3) & 1) * 8 + (lane & 7);
    uint32_t bOff = fmB + (uint32_t)((((lane >> 4) & 1) * 8 >> 1) * 4);

    float acc[4][4];
#pragma unroll
    for (int ni = 0; ni < 4; ni++)
#pragma unroll
        for (int q = 0; q < 4; q++) acc[ni][q] = 0.f;
    float2 nacc = make_float2(0.f, 0.f);
    int ng2 = tid & 31, nr0 = (tid >> 5) * 16;

    for (int ck = 0; ck < 8; ck++) {
        __syncthreads();
#pragma unroll
        for (int j = 0; j < 4; j++) {
            int s = tid + 256 * j;
            int r = s >> 3, c = (s & 7) * 4;
            *(uint4*)&Ssw[r][c] = *(const uint4*)&swp[(size_t)(ck * 128 + r) * 32 + c];
        }
#pragma unroll
        for (int j = 0; j < 2; j++) {
            int s = tid + 256 * j;
            int r = s >> 2, c = (s & 3) * 4;
            *(uint4*)&Sfm[r][c] = *(const uint4*)&fm[(size_t)(ck * 128 + r) * 128 + c];
        }
        __syncthreads();
#pragma unroll
        for (int r = 0; r < 16; r++) {
            __half2 v = *(__half2*)&Ssw[nr0 + r][ng2];
            nacc.x += __low2float(v);
            nacc.y += __high2float(v);
        }
#pragma unroll
        for (int ks = 0; ks < 4; ks++) {
            int nk = kseg + ks * 16;
            uint32_t a[4];
            ldsm4t(a[0], a[1], a[2], a[3], aOff + (uint32_t)((nk + aRow) * 144));
            uint32_t b0[4], b1[4];
            ldsm4t(b0[0], b0[1], b0[2], b0[3], bOff + (uint32_t)((nk + bRow) * 80));
            ldsm4t(b1[0], b1[1], b1[2], b1[3], bOff + (uint32_t)((nk + bRow) * 80 + 32));
            {
                uint32_t bf[2];
                bf[0] = b0[0]; bf[1] = b0[1];
                mma_f16(acc[0], a, bf);
                bf[0] = b0[2]; bf[1] = b0[3];
                mma_f16(acc[1], a, bf);
                bf[0] = b1[0]; bf[1] = b1[1];
                mma_f16(acc[2], a, bf);
                bf[0] = b1[2]; bf[1] = b1[3];
                mma_f16(acc[3], a, bf);
            }
        }
    }
    float* stp = g_st + (size_t)bh * 2048;
    int grow = gseg + (lane >> 2);
#pragma unroll
    for (int ni = 0; ni < 4; ni++) {
        int dcol = ni * 8 + (lane & 3) * 2;
        atomicAdd(&stp[grow * 32 + dcol], acc[ni][0]);
        atomicAdd(&stp[grow * 32 + dcol + 1], acc[ni][1]);
        atomicAdd(&stp[(grow + 8) * 32 + dcol], acc[ni][2]);
        atomicAdd(&stp[(grow + 8) * 32 + dcol + 1], acc[ni][3]);
    }
    atomicAdd(&g_norm[bh * 64 + 2 * ng2], nacc.x);
    atomicAdd(&g_norm[bh * 64 + 2 * ng2 + 1], nacc.y);
}

// normalize st, q/k/v, 64x64 attention; write half2-packed ot (g-pairs)
__global__ void qkv_attn_kernel(const float* __restrict__ wq,
                                const float* __restrict__ wk,
                                const float* __restrict__ wv) {
    int bh = blockIdx.x;
    int tid = threadIdx.x;  // 256
    __shared__ float st_s[2048], q_s[2048], k_s[2048], s_s[4096];
    for (int i = tid; i < 2048; i += 256) {
        int g = i >> 5;
        st_s[i] = g_st[bh * 2048 + i] / (g_norm[bh * 64 + g] + 1e-5f);
    }
    __syncthreads();
    for (int i = tid; i < 2048; i += 256) {
        int g = i >> 5, d = i & 31;
        float aq = 0.f, ak = 0.f;
#pragma unroll
        for (int c = 0; c < 32; c++) {
            float s = st_s[g * 32 + c];
            aq += s * wq[c * 32 + d];
            ak += s * wk[c * 32 + d];
        }
        q_s[i] = aq;
        k_s[i] = ak;
    }
    __syncthreads();
    const float scale = 0.17677669529663687f;
    for (int i = tid; i < 4096; i += 256) {
        int g = i >> 6, j = i & 63;
        float a = 0.f;
#pragma unroll
        for (int d = 0; d < 32; d++) a += q_s[g * 32 + d] * k_s[j * 32 + d];
        s_s[i] = a * scale;
    }
    __syncthreads();
    if (tid < 64) {
        float m = -1e30f;
        for (int j = 0; j < 64; j++) m = fmaxf(m, s_s[tid * 64 + j]);
        float sum = 0.f;
        for (int j = 0; j < 64; j++) {
            float e = expf(s_s[tid * 64 + j] - m);
            s_s[tid * 64 + j] = e;
            sum += e;
        }
        float inv = 1.f / sum;
        for (int j = 0; j < 64; j++) s_s[tid * 64 + j] *= inv;
    }
    __syncthreads();
    for (int i = tid; i < 2048; i += 256) {
        int g = i >> 5, d = i & 31;
        float a = 0.f;
#pragma unroll
        for (int j = 0; j < 64; j++) a += s_s[g * 64 + j] * st_s[j * 32 + d];
        q_s[i] = a;
    }
    __syncthreads();
    for (int i = tid; i < 2048; i += 256) {
        int g = i >> 5, d = i & 31;
        float a = 0.f;
#pragma unroll
        for (int c = 0; c < 32; c++) a += q_s[g * 32 + c] * wv[c * 32 + d];
        k_s[i] = a;
    }
    __syncthreads();
    for (int i = tid; i < 1024; i += 256) {
        int gp = i >> 5, d = i & 31;
        g_otp[bh * 1024 + i] = packh(k_s[(2 * gp) * 32 + d], k_s[(2 * gp + 1) * 32 + d]);
    }
}

// ============ deslice via fp16 mma: outx[128n x 32d] = sw[128n x 64g] @ ot ===
__global__ __launch_bounds__(256, 2)
void deslice_mma_kernel() {
    __shared__ uint32_t As[128][36];
    __shared__ uint32_t Bp[32][33];
    int n0 = blockIdx.x * 128;
    int bh = blockIdx.y;
    int b = bh >> 3, h = bh & 7;
    int tid = threadIdx.x;
    int wid = tid >> 5, lane = tid & 31;
    int wm = wid * 16;
    int gid = lane >> 2, tig = lane & 3;

    const uint32_t* swp = (const uint32_t*)g_swh + ((size_t)bh * Nn + n0) * 32;
#pragma unroll
    for (int j = 0; j < 4; j++) {
        int s = tid + 256 * j;
        int r = s >> 3, c = (s & 7) * 4;
        *(uint4*)&As[r][c] = *(const uint4*)&swp[(size_t)r * 32 + c];
    }
#pragma unroll
    for (int j = 0; j < 4; j++) {
        int s = tid + 256 * j;
        Bp[s >> 5][s & 31] = g_otp[bh * 1024 + s];
    }
    __syncthreads();

    uint32_t smemA = (uint32_t)__cvta_generic_to_shared(&As[0][0]);
    int arow = wm + (lane & 7) + ((lane >> 3) & 1) * 8;
    uint32_t aBase = smemA + (uint32_t)((arow * 36 + ((lane >> 4) << 2)) * 4);

    float acc[4][4];
#pragma unroll
    for (int ni = 0; ni < 4; ni++)
#pragma unroll
        for (int q = 0; q < 4; q++) acc[ni][q] = 0.f;

#pragma unroll
    for (int ks = 0; ks < 4; ks++) {
        uint32_t a[4];
        ldsm4(a[0], a[1], a[2], a[3], aBase + ks * 32);
#pragma unroll
        for (int ni = 0; ni < 4; ni++) {
            uint32_t bfr[2];
            bfr[0] = Bp[ks * 8 + tig][ni * 8 + gid];
            bfr[1] = Bp[ks * 8 + tig + 4][ni * 8 + gid];
            mma_f16(acc[ni], a, bfr);
        }
    }
    int r = n0 + wm + gid;
#pragma unroll
    for (int ni = 0; ni < 4; ni++) {
        int dp = ni * 4 + tig;
        g_outxbf[((size_t)b * Nn + r) * 128 + h * 16 + dp] = packbf(acc[ni][0], acc[ni][1]);
        g_outxbf[((size_t)b * Nn + r + 8) * 128 + h * 16 + dp] = packbf(acc[ni][2], acc[ni][3]);
    }
}

// ---------------- driver ----------------
extern "C" void kernel_launch(void* const* d_in, const int* in_sizes, int n_in,
                              void* d_out, int out_size) {
    const float* fx_in  = (const float*)d_in[0];
    const float* ln1_w  = (const float*)d_in[1];
    const float* ln1_b  = (const float*)d_in[2];
    const float* convx_w  = (const float*)d_in[3];
    const float* convx_b  = (const float*)d_in[4];
    const float* convfx_w = (const float*)d_in[5];
    const float* convfx_b = (const float*)d_in[6];
    const float* slice_w  = (const float*)d_in[7];
    const float* slice_b  = (const float*)d_in[8];
    const float* temperature = (const float*)d_in[9];
    const float* wq = (const float*)d_in[10];
    const float* wk = (const float*)d_in[11];
    const float* wv = (const float*)d_in[12];
    const float* wo = (const float*)d_in[13];
    const float* bo = (const float*)d_in[14];
    const float* ln2_w = (const float*)d_in[15];
    const float* ln2_b = (const float*)d_in[16];
    const float* w1 = (const float*)d_in[17];
    const float* b1 = (const float*)d_in[18];
    const float* w2 = (const float*)d_in[19];
    const float* b2 = (const float*)d_in[20];
    const float* ln3_w = (const float*)d_in[21];
    const float* ln3_b = (const float*)d_in[22];
    const float* w_out = (const float*)d_in[23];
    const float* b_out = (const float*)d_in[24];

    float* p_fx;
    uint32_t *p_lnbf, *p_xmidh, *p_fxmidh, *p_outxbf, *p_hidbf, *p_wpk;
    cudaGetSymbolAddress((void**)&p_fx, g_fx);
    cudaGetSymbolAddress((void**)&p_lnbf, g_lnbf);
    cudaGetSymbolAddress((void**)&p_xmidh, g_xmidh);
    cudaGetSymbolAddress((void**)&p_fxmidh, g_fxmidh);
    cudaGetSymbolAddress((void**)&p_outxbf, g_outxbf);
    cudaGetSymbolAddress((void**)&p_hidbf, g_hidbf);
    cudaGetSymbolAddress((void**)&p_wpk, g_wpk);

    pack_kernel<<<2048, 256>>>(convx_w, p_wpk + WPK_CONVX, 1152, 256, Lnum,
                               (size_t)2304 * 256, WPK_LAYER);
    pack_kernel<<<2048, 256>>>(convfx_w, p_wpk + WPK_CONVFX, 1152, 256, Lnum,
                               (size_t)2304 * 256, WPK_LAYER);
    pack_kernel<<<256, 256>>>(wo, p_wpk + WPK_WO, 128, 256, Lnum,
                              (size_t)256 * 256, WPK_LAYER);
    pack_kernel<<<1024, 256>>>(w1, p_wpk + WPK_W1, 128, 1024, Lnum,
                               (size_t)256 * 1024, WPK_LAYER);
    pack_kernel<<<1024, 256>>>(w2, p_wpk + WPK_W2, 512, 256, Lnum,
                               (size_t)1024 * 256, WPK_LAYER);

    copy_in_kernel<<<ROWS * Cc / 256, 256>>>(fx_in);

    for (int i = 0; i < Lnum; i++) {
        const uint32_t* wl = p_wpk + (size_t)i * WPK_LAYER;
        ln_kernel<<<ROWS, 256>>>(p_fx, p_lnbf, ln1_w + i * Cc, ln1_b + i * Cc);
        dim3 cg(ROWS / 128, 2);
        conv_bf16_kernel<<<cg, 256>>>(p_lnbf, wl + WPK_CONVX, convx_b + i * INNERc, p_xmidh);
        conv_bf16_kernel<<<cg, 256>>>(p_lnbf, wl + WPK_CONVFX, convfx_b + i * INNERc, p_fxmidh);
        slice_softmax_kernel<<<ROWS, 512>>>(p_xmidh, slice_w + i * DHd * Gg,
                                            slice_b + i * Gg, temperature + i * HEADS);
        zero_stats_kernel<<<(Bsz * HEADS * Gg * DHd + 255) / 256, 256>>>();
        st_mma_kernel<<<dim3(Bsz * HEADS, 16), 256>>>();
        qkv_attn_kernel<<<Bsz * HEADS, 256>>>(wq + i * DHd * DHd, wk + i * DHd * DHd,
                                              wv + i * DHd * DHd);
        deslice_mma_kernel<<<dim3(Nn / 128, Bsz * HEADS), 256>>>();
        gemm_bf16_kernel<false, true, false><<<dim3(ROWS / 128, 2), 256>>>(
            p_outxbf, wl + WPK_WO, bo + i * Cc, p_fx, p_fx, nullptr, 128, Cc);
        ln_kernel<<<ROWS, 256>>>(p_fx, p_lnbf, ln2_w + i * Cc, ln2_b + i * Cc);
        gemm_bf16_kernel<true, false, true><<<dim3(ROWS / 128, HIDc / 128), 256>>>(
            p_lnbf, wl + WPK_W1, b1 + i * HIDc, nullptr, nullptr, p_hidbf, 128, HIDc);
        gemm_bf16_kernel<false, true, false><<<dim3(ROWS / 128, 2), 256>>>(
            p_hidbf, wl + WPK_W2, b2 + i * Cc, p_fx, p_fx, nullptr, 512, Cc);
    }

    ln_head_kernel<<<ROWS / 8, 256>>>(p_fx, ln3_w, ln3_b, w_out, b_out, (float*)d_out);
}

// round 15
// speedup vs baseline: 1.5334x; 1.5334x over previous
#include <cuda_runtime.h>
#include <cuda_fp16.h>
#include <stdint.h>
#include <math.h>

#define DEV_INLINE __device__ __forceinline__

constexpr int Bsz = 4, Cc = 256, Hh = 128, Ww = 128, Nn = Hh * Ww;
constexpr int HEADS = 8, DHd = 32, Gg = 64, INNERc = 256, HIDc = 1024;
constexpr int Lnum = 4, OUTc = 4;
constexpr int ROWS = Bsz * Nn;  // 65536

// packed-weight layout (u32 = bf16x2 k-pairs, k-major), per layer offsets
constexpr int WPK_CONVX = 0;                       // Kp=1152, N=256
constexpr int WPK_CONVFX = 1152 * 256;
constexpr int WPK_WO = 2 * 1152 * 256;             // Kp=128, N=256
constexpr int WPK_W1 = WPK_WO + 128 * 256;         // Kp=128, N=1024
constexpr int WPK_W2 = WPK_W1 + 128 * 1024;        // Kp=512, N=256
constexpr int WPK_LAYER = WPK_W2 + 512 * 256;

// ---------------- scratch (device globals; no runtime alloc) ----------------
__device__ float g_fx[ROWS * Cc];
__device__ uint32_t g_lnbf[ROWS * (Cc / 2)];
__device__ uint32_t g_xmidh[ROWS * (INNERc / 2)];
__device__ uint32_t g_fxmidh[ROWS * (INNERc / 2)];
__device__ __half g_swh[(size_t)Bsz * HEADS * Nn * Gg];
__device__ float g_st[Bsz * HEADS * Gg * DHd];
__device__ float g_norm[Bsz * HEADS * Gg];
__device__ uint32_t g_otp[Bsz * HEADS * (Gg / 2) * DHd];
__device__ uint32_t g_outxbf[ROWS * (INNERc / 2)];
__device__ uint32_t g_hidbf[ROWS * (HIDc / 2)];
__device__ uint32_t g_wpk[Lnum * WPK_LAYER];

// ---------------- helpers ----------------
DEV_INLINE float warpSum(float v) {
#pragma unroll
    for (int o = 16; o; o >>= 1) v += __shfl_xor_sync(0xffffffffu, v, o);
    return v;
}
DEV_INLINE float warpMax(float v) {
#pragma unroll
    for (int o = 16; o; o >>= 1) v = fmaxf(v, __shfl_xor_sync(0xffffffffu, v, o));
    return v;
}
DEV_INLINE uint32_t packbf(float lo, float hi) {
    uint32_t r;
    asm("cvt.rn.bf16x2.f32 %0, %1, %2;" : "=r"(r) : "f"(hi), "f"(lo));
    return r;
}
DEV_INLINE uint32_t packh(float lo, float hi) {
    uint32_t r;
    asm("cvt.rn.f16x2.f32 %0, %1, %2;" : "=r"(r) : "f"(hi), "f"(lo));
    return r;
}
DEV_INLINE void mma_bf16(float c[4], const uint32_t a[4], const uint32_t b[2]) {
    asm volatile(
        "mma.sync.aligned.m16n8k16.row.col.f32.bf16.bf16.f32 "
        "{%0,%1,%2,%3}, {%4,%5,%6,%7}, {%8,%9}, {%0,%1,%2,%3};"
        : "+f"(c[0]), "+f"(c[1]), "+f"(c[2]), "+f"(c[3])
        : "r"(a[0]), "r"(a[1]), "r"(a[2]), "r"(a[3]), "r"(b[0]), "r"(b[1]));
}
DEV_INLINE void mma_f16(float c[4], const uint32_t a[4], const uint32_t b[2]) {
    asm volatile(
        "mma.sync.aligned.m16n8k16.row.col.f32.f16.f16.f32 "
        "{%0,%1,%2,%3}, {%4,%5,%6,%7}, {%8,%9}, {%0,%1,%2,%3};"
        : "+f"(c[0]), "+f"(c[1]), "+f"(c[2]), "+f"(c[3])
        : "r"(a[0]), "r"(a[1]), "r"(a[2]), "r"(a[3]), "r"(b[0]), "r"(b[1]));
}
DEV_INLINE void ldsm4(uint32_t& r0, uint32_t& r1, uint32_t& r2, uint32_t& r3,
                      uint32_t addr) {
    asm volatile("ldmatrix.sync.aligned.m8n8.x4.shared.b16 {%0,%1,%2,%3}, [%4];"
                 : "=r"(r0), "=r"(r1), "=r"(r2), "=r"(r3)
                 : "r"(addr));
}
DEV_INLINE void ldsm4t(uint32_t& r0, uint32_t& r1, uint32_t& r2, uint32_t& r3,
                       uint32_t addr) {
    asm volatile("ldmatrix.sync.aligned.m8n8.x4.trans.shared.b16 {%0,%1,%2,%3}, [%4];"
                 : "=r"(r0), "=r"(r1), "=r"(r2), "=r"(r3)
                 : "r"(addr));
}

// ---------------- copy input ----------------
__global__ void copy_in_kernel(const float* __restrict__ src) {
    int i = blockIdx.x * 256 + threadIdx.x;
    g_fx[i] = src[i];
}

// ---------------- weight pre-pack: k-major bf16 k-pair packing --------------
__global__ void pack_kernel(const float* __restrict__ src, uint32_t* __restrict__ dst,
                            int Kp, int N, int L, size_t sstride, size_t dstride) {
    int total = L * Kp * N;
    for (int idx = blockIdx.x * blockDim.x + threadIdx.x; idx < total;
         idx += gridDim.x * blockDim.x) {
        int l = idx / (Kp * N);
        int r = idx - l * (Kp * N);
        int kp = r / N, n = r - kp * N;
        float lo = src[l * sstride + (size_t)(2 * kp) * N + n];
        float hi = src[l * sstride + (size_t)(2 * kp + 1) * N + n];
        dst[l * dstride + (size_t)kp * N + n] = packbf(lo, hi);
    }
}

// ---------------- layernorm over C=256, one block per row (proven) ----------
__global__ void ln_kernel(const float* __restrict__ in, uint32_t* __restrict__ outb,
                          const float* __restrict__ w, const float* __restrict__ b) {
    int row = blockIdx.x;
    int t = threadIdx.x;
    float v = in[row * Cc + t];
    __shared__ float red[8];
    __shared__ float s_mean, s_rstd;
    float s = warpSum(v);
    if ((t & 31) == 0) red[t >> 5] = s;
    __syncthreads();
    if (t < 8) {
        float x = red[t];
#pragma unroll
        for (int o = 4; o; o >>= 1) x += __shfl_xor_sync(0xffu, x, o);
        if (t == 0) s_mean = x * (1.f / Cc);
    }
    __syncthreads();
    float m = s_mean;
    float d = v - m;
    float s2 = warpSum(d * d);
    if ((t & 31) == 0) red[t >> 5] = s2;
    __syncthreads();
    if (t < 8) {
        float x = red[t];
#pragma unroll
        for (int o = 4; o; o >>= 1) x += __shfl_xor_sync(0xffu, x, o);
        if (t == 0) s_rstd = rsqrtf(x * (1.f / Cc) + 1e-5f);
    }
    __syncthreads();
    float o = d * s_rstd * w[t] + b[t];
    float nb = __shfl_xor_sync(0xffffffffu, o, 1);
    if (!(t & 1)) outb[row * (Cc / 2) + (t >> 1)] = packbf(o, nb);
}

// ---------------- fused ln3 + head: out = ln(fx)@w_out + b_out --------------
__global__ void ln_head_kernel(const float* __restrict__ in, const float* __restrict__ lw,
                               const float* __restrict__ lb, const float* __restrict__ wout,
                               const float* __restrict__ bout, float* __restrict__ out) {
    int warp = threadIdx.x >> 5, lane = threadIdx.x & 31;
    int row = blockIdx.x * 8 + warp;
    int c0 = lane * 8;
    const float* rp = in + (size_t)row * Cc + c0;
    float v[8];
    *(float4*)(v) = *(const float4*)rp;
    *(float4*)(v + 4) = *(const float4*)(rp + 4);
    float s = v[0] + v[1] + v[2] + v[3] + v[4] + v[5] + v[6] + v[7];
    float m = warpSum(s) * (1.f / Cc);
    float s2 = 0.f;
#pragma unroll
    for (int j = 0; j < 8; j++) {
        v[j] -= m;
        s2 += v[j] * v[j];
    }
    float rstd = rsqrtf(warpSum(s2) * (1.f / Cc) + 1e-5f);
    float wv[8], bv[8];
    *(float4*)(wv) = *(const float4*)(lw + c0);
    *(float4*)(wv + 4) = *(const float4*)(lw + c0 + 4);
    *(float4*)(bv) = *(const float4*)(lb + c0);
    *(float4*)(bv + 4) = *(const float4*)(lb + c0 + 4);
    float o[8];
#pragma unroll
    for (int j = 0; j < 8; j++) o[j] = v[j] * rstd * wv[j] + bv[j];
    float p[4] = {0.f, 0.f, 0.f, 0.f};
#pragma unroll
    for (int j = 0; j < 8; j++) {
        float4 wr = *(const float4*)&wout[(c0 + j) * 4];
        p[0] += o[j] * wr.x;
        p[1] += o[j] * wr.y;
        p[2] += o[j] * wr.z;
        p[3] += o[j] * wr.w;
    }
#pragma unroll
    for (int oc = 0; oc < 4; oc++) p[oc] = warpSum(p[oc]);
    if (lane == 0) {
        float4 bo4 = *(const float4*)bout;
        *(float4*)&out[(size_t)row * 4] =
            make_float4(p[0] + bo4.x, p[1] + bo4.y, p[2] + bo4.z, p[3] + bo4.w);
    }
}

// ===== bf16 GEMM (R8): dbl-buffered smem, register-staged LDG, 1 sync/chunk ==
constexpr int ABUF = 128 * 20;  // u32 per A stage

template <bool GELU, bool RES, bool BFOUT>
__global__ __launch_bounds__(256, 2)
void gemm_bf16_kernel(const uint32_t* __restrict__ A, const uint32_t* __restrict__ Bw,
                      const float* __restrict__ bias, const float* __restrict__ resid,
                      float* __restrict__ CoutF, uint32_t* __restrict__ CoutB,
                      int Kp, int Nc) {
    __shared__ uint32_t As2[2][128][20];
    __shared__ uint32_t Bs2[2][16][136];
    int tid = threadIdx.x;
    int m0 = blockIdx.x * 128, nc0 = blockIdx.y * 128;
    int wid = tid >> 5, lane = tid & 31;
    int wm = (wid >> 2) * 64, wn = (wid & 3) * 32;
    int gid = lane >> 2, tig = lane & 3;

    uint32_t smemA = (uint32_t)__cvta_generic_to_shared(&As2[0][0][0]);
    int arow = wm + (lane & 7) + ((lane >> 3) & 1) * 8;
    uint32_t aBase = smemA + (uint32_t)((arow * 20 + ((lane >> 4) << 2)) * 4);

    float acc[4][4][4];
#pragma unroll
    for (int mi = 0; mi < 4; mi++)
#pragma unroll
        for (int ni = 0; ni < 4; ni++)
#pragma unroll
            for (int q = 0; q < 4; q++) acc[mi][ni][q] = 0.f;

    uint4 aP[2], bP[2];
#pragma unroll
    for (int j = 0; j < 2; j++) {
        int s = tid + 256 * j;
        aP[j] = *(const uint4*)&A[(size_t)(m0 + (s >> 2)) * Kp + (s & 3) * 4];
        bP[j] = *(const uint4*)&Bw[(size_t)(s >> 5) * Nc + nc0 + (s & 31) * 4];
    }
#pragma unroll
    for (int j = 0; j < 2; j++) {
        int s = tid + 256 * j;
        *(uint4*)&As2[0][s >> 2][(s & 3) * 4] = aP[j];
        *(uint4*)&Bs2[0][s >> 5][(s & 31) * 4] = bP[j];
    }
    __syncthreads();

    int nch = Kp >> 4;
    for (int ch = 0; ch < nch; ch++) {
        int cur = ch & 1;
        if (ch + 1 < nch) {
            int kc = (ch + 1) * 16;
#pragma unroll
            for (int j = 0; j < 2; j++) {
                int s = tid + 256 * j;
                aP[j] = *(const uint4*)&A[(size_t)(m0 + (s >> 2)) * Kp + kc + (s & 3) * 4];
                bP[j] = *(const uint4*)&Bw[(size_t)(kc + (s >> 5)) * Nc + nc0 + (s & 31) * 4];
            }
        }
        uint32_t aB = aBase + cur * (ABUF * 4);
#pragma unroll
        for (int ks = 0; ks < 2; ks++) {
            int kpb = ks * 8;
            uint32_t bf[4][2];
#pragma unroll
            for (int ni = 0; ni < 4; ni++) {
                int n = wn + ni * 8 + gid;
                bf[ni][0] = Bs2[cur][kpb + tig][n];
                bf[ni][1] = Bs2[cur][kpb + tig + 4][n];
            }
#pragma unroll
            for (int mi = 0; mi < 4; mi++) {
                uint32_t a[4];
                ldsm4(a[0], a[1], a[2], a[3], aB + mi * 1280 + ks * 32);
#pragma unroll
                for (int ni = 0; ni < 4; ni++) mma_bf16(acc[mi][ni], a, bf[ni]);
            }
        }
        if (ch + 1 < nch) {
            int nxt = cur ^ 1;
#pragma unroll
            for (int j = 0; j < 2; j++) {
                int s = tid + 256 * j;
                *(uint4*)&As2[nxt][s >> 2][(s & 3) * 4] = aP[j];
                *(uint4*)&Bs2[nxt][s >> 5][(s & 31) * 4] = bP[j];
            }
            __syncthreads();
        }
    }
#pragma unroll
    for (int mi = 0; mi < 4; mi++) {
        int r = m0 + wm + mi * 16 + gid;
#pragma unroll
        for (int ni = 0; ni < 4; ni++) {
            int cb = nc0 + wn + ni * 8 + tig * 2;
            float b0 = bias[cb], b1 = bias[cb + 1];
            float v0 = acc[mi][ni][0] + b0, v1 = acc[mi][ni][1] + b1;
            float v2 = acc[mi][ni][2] + b0, v3 = acc[mi][ni][3] + b1;
            if (GELU) {
                v0 = 0.5f * v0 * (1.f + erff(v0 * 0.70710678118654752f));
                v1 = 0.5f * v1 * (1.f + erff(v1 * 0.70710678118654752f));
                v2 = 0.5f * v2 * (1.f + erff(v2 * 0.70710678118654752f));
                v3 = 0.5f * v3 * (1.f + erff(v3 * 0.70710678118654752f));
            }
            if (RES) {
                v0 += resid[(size_t)r * Nc + cb];
                v1 += resid[(size_t)r * Nc + cb + 1];
                v2 += resid[(size_t)(r + 8) * Nc + cb];
                v3 += resid[(size_t)(r + 8) * Nc + cb + 1];
            }
            if (BFOUT) {
                CoutB[(size_t)r * (Nc / 2) + (cb >> 1)] = packbf(v0, v1);
                CoutB[(size_t)(r + 8) * (Nc / 2) + (cb >> 1)] = packbf(v2, v3);
            } else {
                *(float2*)&CoutF[(size_t)r * Nc + cb] = make_float2(v0, v1);
                *(float2*)&CoutF[(size_t)(r + 8) * Nc + cb] = make_float2(v2, v3);
            }
        }
    }
}

// ===== bf16 conv 3x3 implicit GEMM (R8): dbl-buffered, 72 chunks ============
__global__ __launch_bounds__(256, 2)
void conv_bf16_kernel(const uint32_t* __restrict__ Abf, const uint32_t* __restrict__ Wp,
                      const float* __restrict__ bias, uint32_t* __restrict__ CoutH) {
    __shared__ uint32_t As2[2][128][20];
    __shared__ uint32_t Bs2[2][16][136];
    int tid = threadIdx.x;
    int m0 = blockIdx.x * 128, nc0 = blockIdx.y * 128;
    int b = blockIdx.x >> 7;
    int y = blockIdx.x & 127;
    int wid = tid >> 5, lane = tid & 31;
    int wm = (wid >> 2) * 64, wn = (wid & 3) * 32;
    int gid = lane >> 2, tig = lane & 3;

    uint32_t smemA = (uint32_t)__cvta_generic_to_shared(&As2[0][0][0]);
    int arow = wm + (lane & 7) + ((lane >> 3) & 1) * 8;
    uint32_t aBase = smemA + (uint32_t)((arow * 20 + ((lane >> 4) << 2)) * 4);

    float acc[4][4][4];
#pragma unroll
    for (int mi = 0; mi < 4; mi++)
#pragma unroll
        for (int ni = 0; ni < 4; ni++)
#pragma unroll
            for (int q = 0; q < 4; q++) acc[mi][ni][q] = 0.f;

    uint4 aP[2], bP[2];
    const uint4 z4 = make_uint4(0, 0, 0, 0);
    {
        int yy = y - 1;
#pragma unroll
        for (int j = 0; j < 2; j++) {
            int s = tid + 256 * j;
            int xx = (s >> 2) - 1;
            aP[j] = ((unsigned)yy < 128u && (unsigned)xx < 128u)
                        ? *(const uint4*)&Abf[(size_t)(((b << 7) + yy) * 128 + xx) * 128 +
                                              (s & 3) * 4]
                        : z4;
            bP[j] = *(const uint4*)&Wp[(size_t)(s >> 5) * 256 + nc0 + (s & 31) * 4];
        }
    }
#pragma unroll
    for (int j = 0; j < 2; j++) {
        int s = tid + 256 * j;
        *(uint4*)&As2[0][s >> 2][(s & 3) * 4] = aP[j];
        *(uint4*)&Bs2[0][s >> 5][(s & 31) * 4] = bP[j];
    }
    __syncthreads();

    for (int ch = 0; ch < 72; ch++) {
        int cur = ch & 1;
        if (ch + 1 < 72) {
            int cn = ch + 1;
            int tap = cn >> 3, icp0 = (cn & 7) * 16;
            int dy = tap / 3 - 1, dx = tap % 3 - 1;
            int yy = y + dy;
#pragma unroll
            for (int j = 0; j < 2; j++) {
                int s = tid + 256 * j;
                int xx = (s >> 2) + dx;
                aP[j] = ((unsigned)yy < 128u && (unsigned)xx < 128u)
                            ? *(const uint4*)&Abf[(size_t)(((b << 7) + yy) * 128 + xx) * 128 +
                                                  icp0 + (s & 3) * 4]
                            : z4;
                bP[j] = *(const uint4*)&Wp[(size_t)(tap * 128 + icp0 + (s >> 5)) * 256 + nc0 +
                                           (s & 31) * 4];
            }
        }
        uint32_t aB = aBase + cur * (ABUF * 4);
#pragma unroll
        for (int ks = 0; ks < 2; ks++) {
            int kpb = ks * 8;
            uint32_t bf[4][2];
#pragma unroll
            for (int ni = 0; ni < 4; ni++) {
                int n = wn + ni * 8 + gid;
                bf[ni][0] = Bs2[cur][kpb + tig][n];
                bf[ni][1] = Bs2[cur][kpb + tig + 4][n];
            }
#pragma unroll
            for (int mi = 0; mi < 4; mi++) {
                uint32_t a[4];
                ldsm4(a[0], a[1], a[2], a[3], aB + mi * 1280 + ks * 32);
#pragma unroll
                for (int ni = 0; ni < 4; ni++) mma_bf16(acc[mi][ni], a, bf[ni]);
            }
        }
        if (ch + 1 < 72) {
            int nxt = cur ^ 1;
#pragma unroll
            for (int j = 0; j < 2; j++) {
                int s = tid + 256 * j;
                *(uint4*)&As2[nxt][s >> 2][(s & 3) * 4] = aP[j];
                *(uint4*)&Bs2[nxt][s >> 5][(s & 31) * 4] = bP[j];
            }
            __syncthreads();
        }
    }
#pragma unroll
    for (int mi = 0; mi < 4; mi++) {
        int r = m0 + wm + mi * 16 + gid;
#pragma unroll
        for (int ni = 0; ni < 4; ni++) {
            int cb = nc0 + wn + ni * 8 + tig * 2;
            float b0 = bias[cb], b1 = bias[cb + 1];
            CoutH[(size_t)r * 128 + (cb >> 1)] = packh(acc[mi][ni][0] + b0, acc[mi][ni][1] + b1);
            CoutH[(size_t)(r + 8) * 128 + (cb >> 1)] =
                packh(acc[mi][ni][2] + b0, acc[mi][ni][3] + b1);
        }
    }
}

// ---------------- slice logits + softmax over G=64 ----------------
__global__ void slice_softmax_kernel(const uint32_t* __restrict__ xmidh,
                                     const float* __restrict__ sw_w,
                                     const float* __restrict__ sw_b,
                                     const float* __restrict__ temp) {
    int row = blockIdx.x;
    int b = row >> 14;
    int n = row & (Nn - 1);
    int tid = threadIdx.x;  // 512
    __shared__ float sx[256];
    __shared__ float wred[16];
    if (tid < 128) {
        __half2 v = *(const __half2*)&xmidh[(size_t)row * 128 + tid];
        sx[2 * tid] = __low2float(v);
        sx[2 * tid + 1] = __high2float(v);
    }
    __syncthreads();
    int h = tid >> 6, g = tid & 63;
    const float* xh = sx + h * 32;
    float acc = sw_b[g];
#pragma unroll
    for (int d = 0; d < 32; d++) acc += xh[d] * sw_w[d * 64 + g];
    float tp = fminf(fmaxf(temp[h], 0.1f), 5.0f);
    acc /= tp;
    int wid = tid >> 5, lane = tid & 31;
    float m = warpMax(acc);
    if (lane == 0) wred[wid] = m;
    __syncthreads();
    m = fmaxf(wred[h * 2], wred[h * 2 + 1]);
    float e = expf(acc - m);
    __syncthreads();
    float s = warpSum(e);
    if (lane == 0) wred[wid] = s;
    __syncthreads();
    s = wred[h * 2] + wred[h * 2 + 1];
    g_swh[((size_t)(b * HEADS + h) * Nn + n) * Gg + g] = __float2half(e / s);
}

__global__ void zero_stats_kernel() {
    int i = blockIdx.x * 256 + threadIdx.x;
    if (i < Bsz * HEADS * Gg * DHd) g_st[i] = 0.f;
    if (i < Bsz * HEADS * Gg) g_norm[i] = 0.f;
}

// ===== st via fp16 mma: st[64g][32d] += sw^T @ fxmid ; norm[g] += col-sum ====
__global__ __launch_bounds__(256)
void st_mma_kernel() {
    __shared__ uint32_t Ssw[128][36];
    __shared__ uint32_t Sfm[128][20];
    int bh = blockIdx.x;
    int split = blockIdx.y;
    int b = bh >> 3, h = bh & 7;
    int tid = threadIdx.x;
    int wid = tid >> 5, lane = tid & 31;
    int gseg = (wid & 3) * 16;
    int kseg = (wid >> 2) * 64;

    const uint32_t* swp = (const uint32_t*)g_swh + ((size_t)bh * Nn + split * 1024) * 32;
    const uint32_t* fm = g_fxmidh + (size_t)(b * Nn + split * 1024) * 128 + h * 16;

    uint32_t swB = (uint32_t)__cvta_generic_to_shared(&Ssw[0][0]);
    uint32_t fmB = (uint32_t)__cvta_generic_to_shared(&Sfm[0][0]);
    int aRow = ((lane >> 4) & 1) * 8 + (lane & 7);
    uint32_t aOff = swB + (uint32_t)(((gseg + ((lane >> 3) & 1) * 8) >> 1) * 4);
    int bRow = ((lane >> 3) & 1) * 8 + (lane & 7);
    uint32_t bOff = fmB + (uint32_t)((((lane >> 4) & 1) * 8 >> 1) * 4);

    float acc[4][4];
#pragma unroll
    for (int ni = 0; ni < 4; ni++)
#pragma unroll
        for (int q = 0; q < 4; q++) acc[ni][q] = 0.f;
    float2 nacc = make_float2(0.f, 0.f);
    int ng2 = tid & 31, nr0 = (tid >> 5) * 16;

    for (int ck = 0; ck < 8; ck++) {
        __syncthreads();
#pragma unroll
        for (int j = 0; j < 4; j++) {
            int s = tid + 256 * j;
            int r = s >> 3, c = (s & 7) * 4;
            *(uint4*)&Ssw[r][c] = *(const uint4*)&swp[(size_t)(ck * 128 + r) * 32 + c];
        }
#pragma unroll
        for (int j = 0; j < 2; j++) {
            int s = tid + 256 * j;
            int r = s >> 2, c = (s & 3) * 4;
            *(uint4*)&Sfm[r][c] = *(const uint4*)&fm[(size_t)(ck * 128 + r) * 128 + c];
        }
        __syncthreads();
#pragma unroll
        for (int r = 0; r < 16; r++) {
            __half2 v = *(__half2*)&Ssw[nr0 + r][ng2];
            nacc.x += __low2float(v);
            nacc.y += __high2float(v);
        }
#pragma unroll
        for (int ks = 0; ks < 4; ks++) {
            int nk = kseg + ks * 16;
            uint32_t a[4];
            ldsm4t(a[0], a[1], a[2], a[3], aOff + (uint32_t)((nk + aRow) * 144));
            uint32_t b0[4], b1[4];
            ldsm4t(b0[0], b0[1], b0[2], b0[3], bOff + (uint32_t)((nk + bRow) * 80));
            ldsm4t(b1[0], b1[1], b1[2], b1[3], bOff + (uint32_t)((nk + bRow) * 80 + 32));
            {
                uint32_t bf[2];
                bf[0] = b0[0]; bf[1] = b0[1];
                mma_f16(acc[0], a, bf);
                bf[0] = b0[2]; bf[1] = b0[3];
                mma_f16(acc[1], a, bf);
                bf[0] = b1[0]; bf[1] = b1[1];
                mma_f16(acc[2], a, bf);
                bf[0] = b1[2]; bf[1] = b1[3];
                mma_f16(acc[3], a, bf);
            }
        }
    }
    float* stp = g_st + (size_t)bh * 2048;
    int grow = gseg + (lane >> 2);
#pragma unroll
    for (int ni = 0; ni < 4; ni++) {
        int dcol = ni * 8 + (lane & 3) * 2;
        atomicAdd(&stp[grow * 32 + dcol], acc[ni][0]);
        atomicAdd(&stp[grow * 32 + dcol + 1], acc[ni][1]);
        atomicAdd(&stp[(grow + 8) * 32 + dcol], acc[ni][2]);
        atomicAdd(&stp[(grow + 8) * 32 + dcol + 1], acc[ni][3]);
    }
    atomicAdd(&g_norm[bh * 64 + 2 * ng2], nacc.x);
    atomicAdd(&g_norm[bh * 64 + 2 * ng2 + 1], nacc.y);
}

// normalize st, q/k/v, 64x64 attention; write half2-packed ot (g-pairs)
__global__ void qkv_attn_kernel(const float* __restrict__ wq,
                                const float* __restrict__ wk,
                                const float* __restrict__ wv) {
    int bh = blockIdx.x;
    int tid = threadIdx.x;  // 256
    __shared__ float st_s[2048], q_s[2048], k_s[2048], s_s[4096];
    for (int i = tid; i < 2048; i += 256) {
        int g = i >> 5;
        st_s[i] = g_st[bh * 2048 + i] / (g_norm[bh * 64 + g] + 1e-5f);
    }
    __syncthreads();
    for (int i = tid; i < 2048; i += 256) {
        int g = i >> 5, d = i & 31;
        float aq = 0.f, ak = 0.f;
#pragma unroll
        for (int c = 0; c < 32; c++) {
            float s = st_s[g * 32 + c];
            aq += s * wq[c * 32 + d];
            ak += s * wk[c * 32 + d];
        }
        q_s[i] = aq;
        k_s[i] = ak;
    }
    __syncthreads();
    const float scale = 0.17677669529663687f;
    for (int i = tid; i < 4096; i += 256) {
        int g = i >> 6, j = i & 63;
        float a = 0.f;
#pragma unroll
        for (int d = 0; d < 32; d++) a += q_s[g * 32 + d] * k_s[j * 32 + d];
        s_s[i] = a * scale;
    }
    __syncthreads();
    if (tid < 64) {
        float m = -1e30f;
        for (int j = 0; j < 64; j++) m = fmaxf(m, s_s[tid * 64 + j]);
        float sum = 0.f;
        for (int j = 0; j < 64; j++) {
            float e = expf(s_s[tid * 64 + j] - m);
            s_s[tid * 64 + j] = e;
            sum += e;
        }
        float inv = 1.f / sum;
        for (int j = 0; j < 64; j++) s_s[tid * 64 + j] *= inv;
    }
    __syncthreads();
    for (int i = tid; i < 2048; i += 256) {
        int g = i >> 5, d = i & 31;
        float a = 0.f;
#pragma unroll
        for (int j = 0; j < 64; j++) a += s_s[g * 64 + j] * st_s[j * 32 + d];
        q_s[i] = a;
    }
    __syncthreads();
    for (int i = tid; i < 2048; i += 256) {
        int g = i >> 5, d = i & 31;
        float a = 0.f;
#pragma unroll
        for (int c = 0; c < 32; c++) a += q_s[g * 32 + c] * wv[c * 32 + d];
        k_s[i] = a;
    }
    __syncthreads();
    for (int i = tid; i < 1024; i += 256) {
        int gp = i >> 5, d = i & 31;
        g_otp[bh * 1024 + i] = packh(k_s[(2 * gp) * 32 + d], k_s[(2 * gp + 1) * 32 + d]);
    }
}

// ============ deslice via fp16 mma: outx[128n x 32d] = sw[128n x 64g] @ ot ===
__global__ __launch_bounds__(256, 2)
void deslice_mma_kernel() {
    __shared__ uint32_t As[128][36];
    __shared__ uint32_t Bp[32][33];
    int n0 = blockIdx.x * 128;
    int bh = blockIdx.y;
    int b = bh >> 3, h = bh & 7;
    int tid = threadIdx.x;
    int wid = tid >> 5, lane = tid & 31;
    int wm = wid * 16;
    int gid = lane >> 2, tig = lane & 3;

    const uint32_t* swp = (const uint32_t*)g_swh + ((size_t)bh * Nn + n0) * 32;
#pragma unroll
    for (int j = 0; j < 4; j++) {
        int s = tid + 256 * j;
        int r = s >> 3, c = (s & 7) * 4;
        *(uint4*)&As[r][c] = *(const uint4*)&swp[(size_t)r * 32 + c];
    }
#pragma unroll
    for (int j = 0; j < 4; j++) {
        int s = tid + 256 * j;
        Bp[s >> 5][s & 31] = g_otp[bh * 1024 + s];
    }
    __syncthreads();

    uint32_t smemA = (uint32_t)__cvta_generic_to_shared(&As[0][0]);
    int arow = wm + (lane & 7) + ((lane >> 3) & 1) * 8;
    uint32_t aBase = smemA + (uint32_t)((arow * 36 + ((lane >> 4) << 2)) * 4);

    float acc[4][4];
#pragma unroll
    for (int ni = 0; ni < 4; ni++)
#pragma unroll
        for (int q = 0; q < 4; q++) acc[ni][q] = 0.f;

#pragma unroll
    for (int ks = 0; ks < 4; ks++) {
        uint32_t a[4];
        ldsm4(a[0], a[1], a[2], a[3], aBase + ks * 32);
#pragma unroll
        for (int ni = 0; ni < 4; ni++) {
            uint32_t bfr[2];
            bfr[0] = Bp[ks * 8 + tig][ni * 8 + gid];
            bfr[1] = Bp[ks * 8 + tig + 4][ni * 8 + gid];
            mma_f16(acc[ni], a, bfr);
        }
    }
    int r = n0 + wm + gid;
#pragma unroll
    for (int ni = 0; ni < 4; ni++) {
        int dp = ni * 4 + tig;
        g_outxbf[((size_t)b * Nn + r) * 128 + h * 16 + dp] = packbf(acc[ni][0], acc[ni][1]);
        g_outxbf[((size_t)b * Nn + r + 8) * 128 + h * 16 + dp] = packbf(acc[ni][2], acc[ni][3]);
    }
}

// ---------------- driver ----------------
extern "C" void kernel_launch(void* const* d_in, const int* in_sizes, int n_in,
                              void* d_out, int out_size) {
    const float* fx_in  = (const float*)d_in[0];
    const float* ln1_w  = (const float*)d_in[1];
    const float* ln1_b  = (const float*)d_in[2];
    const float* convx_w  = (const float*)d_in[3];
    const float* convx_b  = (const float*)d_in[4];
    const float* convfx_w = (const float*)d_in[5];
    const float* convfx_b = (const float*)d_in[6];
    const float* slice_w  = (const float*)d_in[7];
    const float* slice_b  = (const float*)d_in[8];
    const float* temperature = (const float*)d_in[9];
    const float* wq = (const float*)d_in[10];
    const float* wk = (const float*)d_in[11];
    const float* wv = (const float*)d_in[12];
    const float* wo = (const float*)d_in[13];
    const float* bo = (const float*)d_in[14];
    const float* ln2_w = (const float*)d_in[15];
    const float* ln2_b = (const float*)d_in[16];
    const float* w1 = (const float*)d_in[17];
    const float* b1 = (const float*)d_in[18];
    const float* w2 = (const float*)d_in[19];
    const float* b2 = (const float*)d_in[20];
    const float* ln3_w = (const float*)d_in[21];
    const float* ln3_b = (const float*)d_in[22];
    const float* w_out = (const float*)d_in[23];
    const float* b_out = (const float*)d_in[24];

    float* p_fx;
    uint32_t *p_lnbf, *p_xmidh, *p_fxmidh, *p_outxbf, *p_hidbf, *p_wpk;
    cudaGetSymbolAddress((void**)&p_fx, g_fx);
    cudaGetSymbolAddress((void**)&p_lnbf, g_lnbf);
    cudaGetSymbolAddress((void**)&p_xmidh, g_xmidh);
    cudaGetSymbolAddress((void**)&p_fxmidh, g_fxmidh);
    cudaGetSymbolAddress((void**)&p_outxbf, g_outxbf);
    cudaGetSymbolAddress((void**)&p_hidbf, g_hidbf);
    cudaGetSymbolAddress((void**)&p_wpk, g_wpk);

    pack_kernel<<<2048, 256>>>(convx_w, p_wpk + WPK_CONVX, 1152, 256, Lnum,
                               (size_t)2304 * 256, WPK_LAYER);
    pack_kernel<<<2048, 256>>>(convfx_w, p_wpk + WPK_CONVFX, 1152, 256, Lnum,
                               (size_t)2304 * 256, WPK_LAYER);
    pack_kernel<<<256, 256>>>(wo, p_wpk + WPK_WO, 128, 256, Lnum,
                              (size_t)256 * 256, WPK_LAYER);
    pack_kernel<<<1024, 256>>>(w1, p_wpk + WPK_W1, 128, 1024, Lnum,
                               (size_t)256 * 1024, WPK_LAYER);
    pack_kernel<<<1024, 256>>>(w2, p_wpk + WPK_W2, 512, 256, Lnum,
                               (size_t)1024 * 256, WPK_LAYER);

    copy_in_kernel<<<ROWS * Cc / 256, 256>>>(fx_in);

    for (int i = 0; i < Lnum; i++) {
        const uint32_t* wl = p_wpk + (size_t)i * WPK_LAYER;
        ln_kernel<<<ROWS, 256>>>(p_fx, p_lnbf, ln1_w + i * Cc, ln1_b + i * Cc);
        dim3 cg(ROWS / 128, 2);
        conv_bf16_kernel<<<cg, 256>>>(p_lnbf, wl + WPK_CONVX, convx_b + i * INNERc, p_xmidh);
        conv_bf16_kernel<<<cg, 256>>>(p_lnbf, wl + WPK_CONVFX, convfx_b + i * INNERc, p_fxmidh);
        slice_softmax_kernel<<<ROWS, 512>>>(p_xmidh, slice_w + i * DHd * Gg,
                                            slice_b + i * Gg, temperature + i * HEADS);
        zero_stats_kernel<<<(Bsz * HEADS * Gg * DHd + 255) / 256, 256>>>();
        st_mma_kernel<<<dim3(Bsz * HEADS, 16), 256>>>();
        qkv_attn_kernel<<<Bsz * HEADS, 256>>>(wq + i * DHd * DHd, wk + i * DHd * DHd,
                                              wv + i * DHd * DHd);
        deslice_mma_kernel<<<dim3(Nn / 128, Bsz * HEADS), 256>>>();
        gemm_bf16_kernel<false, true, false><<<dim3(ROWS / 128, 2), 256>>>(
            p_outxbf, wl + WPK_WO, bo + i * Cc, p_fx, p_fx, nullptr, 128, Cc);
        ln_kernel<<<ROWS, 256>>>(p_fx, p_lnbf, ln2_w + i * Cc, ln2_b + i * Cc);
        gemm_bf16_kernel<true, false, true><<<dim3(ROWS / 128, HIDc / 128), 256>>>(
            p_lnbf, wl + WPK_W1, b1 + i * HIDc, nullptr, nullptr, p_hidbf, 128, HIDc);
        gemm_bf16_kernel<false, true, false><<<dim3(ROWS / 128, 2), 256>>>(
            p_hidbf, wl + WPK_W2, b2 + i * Cc, p_fx, p_fx, nullptr, 512, Cc);
    }

    ln_head_kernel<<<ROWS / 8, 256>>>(p_fx, ln3_w, ln3_b, w_out, b_out, (float*)d_out);
}

// round 16
// speedup vs baseline: 1.5738x; 1.0264x over previous
#include <cuda_runtime.h>
#include <cuda_fp16.h>
#include <stdint.h>
#include <math.h>

#define DEV_INLINE __device__ __forceinline__

constexpr int Bsz = 4, Cc = 256, Hh = 128, Ww = 128, Nn = Hh * Ww;
constexpr int HEADS = 8, DHd = 32, Gg = 64, INNERc = 256, HIDc = 1024;
constexpr int Lnum = 4, OUTc = 4;
constexpr int ROWS = Bsz * Nn;  // 65536

// packed-weight layout (u32 = bf16x2 k-pairs, k-major), per layer offsets
constexpr int WPK_CONVX = 0;                       // Kp=1152, N=256
constexpr int WPK_CONVFX = 1152 * 256;
constexpr int WPK_WO = 2 * 1152 * 256;             // Kp=128, N=256
constexpr int WPK_W1 = WPK_WO + 128 * 256;         // Kp=128, N=1024
constexpr int WPK_W2 = WPK_W1 + 128 * 1024;        // Kp=512, N=256
constexpr int WPK_LAYER = WPK_W2 + 512 * 256;

// ---------------- scratch (device globals; no runtime alloc) ----------------
__device__ float g_fx[ROWS * Cc];
__device__ uint32_t g_lnbf[ROWS * (Cc / 2)];
__device__ uint32_t g_xmidh[ROWS * (INNERc / 2)];
__device__ uint32_t g_fxmidh[ROWS * (INNERc / 2)];
__device__ __half g_swh[(size_t)Bsz * HEADS * Nn * Gg];
__device__ float g_st[Bsz * HEADS * Gg * DHd];
__device__ float g_norm[Bsz * HEADS * Gg];
__device__ uint32_t g_otp[Bsz * HEADS * (Gg / 2) * DHd];
__device__ uint32_t g_outxbf[ROWS * (INNERc / 2)];
__device__ uint32_t g_hidbf[ROWS * (HIDc / 2)];
__device__ uint32_t g_wpk[Lnum * WPK_LAYER];

// ---------------- helpers ----------------
DEV_INLINE float warpSum(float v) {
#pragma unroll
    for (int o = 16; o; o >>= 1) v += __shfl_xor_sync(0xffffffffu, v, o);
    return v;
}
DEV_INLINE float warpMax(float v) {
#pragma unroll
    for (int o = 16; o; o >>= 1) v = fmaxf(v, __shfl_xor_sync(0xffffffffu, v, o));
    return v;
}
DEV_INLINE uint32_t packbf(float lo, float hi) {
    uint32_t r;
    asm("cvt.rn.bf16x2.f32 %0, %1, %2;" : "=r"(r) : "f"(hi), "f"(lo));
    return r;
}
DEV_INLINE uint32_t packh(float lo, float hi) {
    uint32_t r;
    asm("cvt.rn.f16x2.f32 %0, %1, %2;" : "=r"(r) : "f"(hi), "f"(lo));
    return r;
}
DEV_INLINE void mma_bf16(float c[4], const uint32_t a[4], const uint32_t b[2]) {
    asm volatile(
        "mma.sync.aligned.m16n8k16.row.col.f32.bf16.bf16.f32 "
        "{%0,%1,%2,%3}, {%4,%5,%6,%7}, {%8,%9}, {%0,%1,%2,%3};"
        : "+f"(c[0]), "+f"(c[1]), "+f"(c[2]), "+f"(c[3])
        : "r"(a[0]), "r"(a[1]), "r"(a[2]), "r"(a[3]), "r"(b[0]), "r"(b[1]));
}
DEV_INLINE void mma_f16(float c[4], const uint32_t a[4], const uint32_t b[2]) {
    asm volatile(
        "mma.sync.aligned.m16n8k16.row.col.f32.f16.f16.f32 "
        "{%0,%1,%2,%3}, {%4,%5,%6,%7}, {%8,%9}, {%0,%1,%2,%3};"
        : "+f"(c[0]), "+f"(c[1]), "+f"(c[2]), "+f"(c[3])
        : "r"(a[0]), "r"(a[1]), "r"(a[2]), "r"(a[3]), "r"(b[0]), "r"(b[1]));
}
DEV_INLINE void ldsm4(uint32_t& r0, uint32_t& r1, uint32_t& r2, uint32_t& r3,
                      uint32_t addr) {
    asm volatile("ldmatrix.sync.aligned.m8n8.x4.shared.b16 {%0,%1,%2,%3}, [%4];"
                 : "=r"(r0), "=r"(r1), "=r"(r2), "=r"(r3)
                 : "r"(addr));
}
DEV_INLINE void ldsm4t(uint32_t& r0, uint32_t& r1, uint32_t& r2, uint32_t& r3,
                       uint32_t addr) {
    asm volatile("ldmatrix.sync.aligned.m8n8.x4.trans.shared.b16 {%0,%1,%2,%3}, [%4];"
                 : "=r"(r0), "=r"(r1), "=r"(r2), "=r"(r3)
                 : "r"(addr));
}

// ---------------- copy input ----------------
__global__ void copy_in_kernel(const float* __restrict__ src) {
    int i = blockIdx.x * 256 + threadIdx.x;
    g_fx[i] = src[i];
}

// ---------------- weight pre-pack: k-major bf16 k-pair packing --------------
__global__ void pack_kernel(const float* __restrict__ src, uint32_t* __restrict__ dst,
                            int Kp, int N, int L, size_t sstride, size_t dstride) {
    int total = L * Kp * N;
    for (int idx = blockIdx.x * blockDim.x + threadIdx.x; idx < total;
         idx += gridDim.x * blockDim.x) {
        int l = idx / (Kp * N);
        int r = idx - l * (Kp * N);
        int kp = r / N, n = r - kp * N;
        float lo = src[l * sstride + (size_t)(2 * kp) * N + n];
        float hi = src[l * sstride + (size_t)(2 * kp + 1) * N + n];
        dst[l * dstride + (size_t)kp * N + n] = packbf(lo, hi);
    }
}

// ---------------- layernorm over C=256, one block per row (proven) ----------
__global__ void ln_kernel(const float* __restrict__ in, uint32_t* __restrict__ outb,
                          const float* __restrict__ w, const float* __restrict__ b) {
    int row = blockIdx.x;
    int t = threadIdx.x;
    float v = in[row * Cc + t];
    __shared__ float red[8];
    __shared__ float s_mean, s_rstd;
    float s = warpSum(v);
    if ((t & 31) == 0) red[t >> 5] = s;
    __syncthreads();
    if (t < 8) {
        float x = red[t];
#pragma unroll
        for (int o = 4; o; o >>= 1) x += __shfl_xor_sync(0xffu, x, o);
        if (t == 0) s_mean = x * (1.f / Cc);
    }
    __syncthreads();
    float m = s_mean;
    float d = v - m;
    float s2 = warpSum(d * d);
    if ((t & 31) == 0) red[t >> 5] = s2;
    __syncthreads();
    if (t < 8) {
        float x = red[t];
#pragma unroll
        for (int o = 4; o; o >>= 1) x += __shfl_xor_sync(0xffu, x, o);
        if (t == 0) s_rstd = rsqrtf(x * (1.f / Cc) + 1e-5f);
    }
    __syncthreads();
    float o = d * s_rstd * w[t] + b[t];
    float nb = __shfl_xor_sync(0xffffffffu, o, 1);
    if (!(t & 1)) outb[row * (Cc / 2) + (t >> 1)] = packbf(o, nb);
}

// ---------------- fused ln3 + head: out = ln(fx)@w_out + b_out --------------
__global__ void ln_head_kernel(const float* __restrict__ in, const float* __restrict__ lw,
                               const float* __restrict__ lb, const float* __restrict__ wout,
                               const float* __restrict__ bout, float* __restrict__ out) {
    int warp = threadIdx.x >> 5, lane = threadIdx.x & 31;
    int row = blockIdx.x * 8 + warp;
    int c0 = lane * 8;
    const float* rp = in + (size_t)row * Cc + c0;
    float v[8];
    *(float4*)(v) = *(const float4*)rp;
    *(float4*)(v + 4) = *(const float4*)(rp + 4);
    float s = v[0] + v[1] + v[2] + v[3] + v[4] + v[5] + v[6] + v[7];
    float m = warpSum(s) * (1.f / Cc);
    float s2 = 0.f;
#pragma unroll
    for (int j = 0; j < 8; j++) {
        v[j] -= m;
        s2 += v[j] * v[j];
    }
    float rstd = rsqrtf(warpSum(s2) * (1.f / Cc) + 1e-5f);
    float wv[8], bv[8];
    *(float4*)(wv) = *(const float4*)(lw + c0);
    *(float4*)(wv + 4) = *(const float4*)(lw + c0 + 4);
    *(float4*)(bv) = *(const float4*)(lb + c0);
    *(float4*)(bv + 4) = *(const float4*)(lb + c0 + 4);
    float o[8];
#pragma unroll
    for (int j = 0; j < 8; j++) o[j] = v[j] * rstd * wv[j] + bv[j];
    float p[4] = {0.f, 0.f, 0.f, 0.f};
#pragma unroll
    for (int j = 0; j < 8; j++) {
        float4 wr = *(const float4*)&wout[(c0 + j) * 4];
        p[0] += o[j] * wr.x;
        p[1] += o[j] * wr.y;
        p[2] += o[j] * wr.z;
        p[3] += o[j] * wr.w;
    }
#pragma unroll
    for (int oc = 0; oc < 4; oc++) p[oc] = warpSum(p[oc]);
    if (lane == 0) {
        float4 bo4 = *(const float4*)bout;
        *(float4*)&out[(size_t)row * 4] =
            make_float4(p[0] + bo4.x, p[1] + bo4.y, p[2] + bo4.z, p[3] + bo4.w);
    }
}

// ===== bf16 GEMM (R8): dbl-buffered smem, register-staged LDG, 1 sync/chunk ==
constexpr int ABUF = 128 * 20;  // u32 per A stage

template <bool GELU, bool RES, bool BFOUT>
__global__ __launch_bounds__(256, 2)
void gemm_bf16_kernel(const uint32_t* __restrict__ A, const uint32_t* __restrict__ Bw,
                      const float* __restrict__ bias, const float* __restrict__ resid,
                      float* __restrict__ CoutF, uint32_t* __restrict__ CoutB,
                      int Kp, int Nc) {
    __shared__ uint32_t As2[2][128][20];
    __shared__ uint32_t Bs2[2][16][136];
    int tid = threadIdx.x;
    int m0 = blockIdx.x * 128, nc0 = blockIdx.y * 128;
    int wid = tid >> 5, lane = tid & 31;
    int wm = (wid >> 2) * 64, wn = (wid & 3) * 32;
    int gid = lane >> 2, tig = lane & 3;

    uint32_t smemA = (uint32_t)__cvta_generic_to_shared(&As2[0][0][0]);
    int arow = wm + (lane & 7) + ((lane >> 3) & 1) * 8;
    uint32_t aBase = smemA + (uint32_t)((arow * 20 + ((lane >> 4) << 2)) * 4);

    float acc[4][4][4];
#pragma unroll
    for (int mi = 0; mi < 4; mi++)
#pragma unroll
        for (int ni = 0; ni < 4; ni++)
#pragma unroll
            for (int q = 0; q < 4; q++) acc[mi][ni][q] = 0.f;

    uint4 aP[2], bP[2];
#pragma unroll
    for (int j = 0; j < 2; j++) {
        int s = tid + 256 * j;
        aP[j] = *(const uint4*)&A[(size_t)(m0 + (s >> 2)) * Kp + (s & 3) * 4];
        bP[j] = *(const uint4*)&Bw[(size_t)(s >> 5) * Nc + nc0 + (s & 31) * 4];
    }
#pragma unroll
    for (int j = 0; j < 2; j++) {
        int s = tid + 256 * j;
        *(uint4*)&As2[0][s >> 2][(s & 3) * 4] = aP[j];
        *(uint4*)&Bs2[0][s >> 5][(s & 31) * 4] = bP[j];
    }
    __syncthreads();

    int nch = Kp >> 4;
    for (int ch = 0; ch < nch; ch++) {
        int cur = ch & 1;
        if (ch + 1 < nch) {
            int kc = (ch + 1) * 16;
#pragma unroll
            for (int j = 0; j < 2; j++) {
                int s = tid + 256 * j;
                aP[j] = *(const uint4*)&A[(size_t)(m0 + (s >> 2)) * Kp + kc + (s & 3) * 4];
                bP[j] = *(const uint4*)&Bw[(size_t)(kc + (s >> 5)) * Nc + nc0 + (s & 31) * 4];
            }
        }
        uint32_t aB = aBase + cur * (ABUF * 4);
#pragma unroll
        for (int ks = 0; ks < 2; ks++) {
            int kpb = ks * 8;
            uint32_t bf[4][2];
#pragma unroll
            for (int ni = 0; ni < 4; ni++) {
                int n = wn + ni * 8 + gid;
                bf[ni][0] = Bs2[cur][kpb + tig][n];
                bf[ni][1] = Bs2[cur][kpb + tig + 4][n];
            }
#pragma unroll
            for (int mi = 0; mi < 4; mi++) {
                uint32_t a[4];
                ldsm4(a[0], a[1], a[2], a[3], aB + mi * 1280 + ks * 32);
#pragma unroll
                for (int ni = 0; ni < 4; ni++) mma_bf16(acc[mi][ni], a, bf[ni]);
            }
        }
        if (ch + 1 < nch) {
            int nxt = cur ^ 1;
#pragma unroll
            for (int j = 0; j < 2; j++) {
                int s = tid + 256 * j;
                *(uint4*)&As2[nxt][s >> 2][(s & 3) * 4] = aP[j];
                *(uint4*)&Bs2[nxt][s >> 5][(s & 31) * 4] = bP[j];
            }
            __syncthreads();
        }
    }
#pragma unroll
    for (int mi = 0; mi < 4; mi++) {
        int r = m0 + wm + mi * 16 + gid;
#pragma unroll
        for (int ni = 0; ni < 4; ni++) {
            int cb = nc0 + wn + ni * 8 + tig * 2;
            float b0 = bias[cb], b1 = bias[cb + 1];
            float v0 = acc[mi][ni][0] + b0, v1 = acc[mi][ni][1] + b1;
            float v2 = acc[mi][ni][2] + b0, v3 = acc[mi][ni][3] + b1;
            if (GELU) {
                v0 = 0.5f * v0 * (1.f + erff(v0 * 0.70710678118654752f));
                v1 = 0.5f * v1 * (1.f + erff(v1 * 0.70710678118654752f));
                v2 = 0.5f * v2 * (1.f + erff(v2 * 0.70710678118654752f));
                v3 = 0.5f * v3 * (1.f + erff(v3 * 0.70710678118654752f));
            }
            if (RES) {
                v0 += resid[(size_t)r * Nc + cb];
                v1 += resid[(size_t)r * Nc + cb + 1];
                v2 += resid[(size_t)(r + 8) * Nc + cb];
                v3 += resid[(size_t)(r + 8) * Nc + cb + 1];
            }
            if (BFOUT) {
                CoutB[(size_t)r * (Nc / 2) + (cb >> 1)] = packbf(v0, v1);
                CoutB[(size_t)(r + 8) * (Nc / 2) + (cb >> 1)] = packbf(v2, v3);
            } else {
                *(float2*)&CoutF[(size_t)r * Nc + cb] = make_float2(v0, v1);
                *(float2*)&CoutF[(size_t)(r + 8) * Nc + cb] = make_float2(v2, v3);
            }
        }
    }
}

// ===== bf16 conv 3x3 implicit GEMM with A-halo reuse =========================
// 24 stages of (dy, icp): A tile [130 px][16 kp] serves all 3 dx taps via
// shifted LDSM bases; B staged for the 3 taps together. smem row r = px (r-1).
constexpr int HA_ASTG = 130 * 20;        // u32 per A stage
constexpr int HA_BSTG = 3 * 16 * 136;    // u32 per B stage
constexpr int HA_SMEM = 2 * (HA_ASTG + HA_BSTG) * 4;  // 73024 B

__global__ __launch_bounds__(256, 2)
void conv_bf16_kernel(const uint32_t* __restrict__ Abf, const uint32_t* __restrict__ Wp,
                      const float* __restrict__ bias, uint32_t* __restrict__ CoutH) {
    extern __shared__ uint32_t sm[];
    uint32_t* smA = sm;                  // [2][130][20]
    uint32_t* smB = sm + 2 * HA_ASTG;    // [2][3][16][136]
    int tid = threadIdx.x;
    int m0 = blockIdx.x * 128, nc0 = blockIdx.y * 128;
    int b = blockIdx.x >> 7;
    int y = blockIdx.x & 127;
    int wid = tid >> 5, lane = tid & 31;
    int wm = (wid >> 2) * 64, wn = (wid & 3) * 32;
    int gid = lane >> 2, tig = lane & 3;

    uint32_t smemA = (uint32_t)__cvta_generic_to_shared(smA);
    int arow = wm + (lane & 7) + ((lane >> 3) & 1) * 8;
    uint32_t aBase = smemA + (uint32_t)((arow * 20 + ((lane >> 4) << 2)) * 4);

    float acc[4][4][4];
#pragma unroll
    for (int mi = 0; mi < 4; mi++)
#pragma unroll
        for (int ni = 0; ni < 4; ni++)
#pragma unroll
            for (int q = 0; q < 4; q++) acc[mi][ni][q] = 0.f;

    uint4 aR[3], bR[6];
    const uint4 z4 = make_uint4(0, 0, 0, 0);

    // prologue: stage 0 = (dy=-1, icp0=0)
    {
        int yy = y - 1;
#pragma unroll
        for (int j = 0; j < 3; j++) {
            int s = tid + 256 * j;
            if (j < 2 || tid < 8) {
                int r = s >> 2, kq = (s & 3) * 4;
                int xx = r - 1;
                aR[j] = ((unsigned)yy < 128u && (unsigned)xx < 128u)
                            ? *(const uint4*)&Abf[(size_t)(((b << 7) + yy) * 128 + xx) * 128 + kq]
                            : z4;
            }
        }
#pragma unroll
        for (int j = 0; j < 6; j++) {
            int s = tid + 256 * j;
            int tapl = s >> 9, st2 = s & 511;
            int kb = st2 >> 5, nq = (st2 & 31) * 4;
            bR[j] = *(const uint4*)&Wp[(size_t)(tapl * 128 + kb) * 256 + nc0 + nq];
        }
#pragma unroll
        for (int j = 0; j < 3; j++) {
            int s = tid + 256 * j;
            if (j < 2 || tid < 8)
                *(uint4*)&smA[(s >> 2) * 20 + (s & 3) * 4] = aR[j];
        }
#pragma unroll
        for (int j = 0; j < 6; j++) {
            int s = tid + 256 * j;
            int tapl = s >> 9, st2 = s & 511;
            *(uint4*)&smB[tapl * 2176 + (st2 >> 5) * 136 + (st2 & 31) * 4] = bR[j];
        }
    }
    __syncthreads();

    for (int st = 0; st < 24; st++) {
        int cur = st & 1;
        if (st + 1 < 24) {
            int ns = st + 1;
            int dyi = ns >> 3, icp0 = (ns & 7) * 16;
            int yy = y + dyi - 1;
#pragma unroll
            for (int j = 0; j < 3; j++) {
                int s = tid + 256 * j;
                if (j < 2 || tid < 8) {
                    int r = s >> 2, kq = (s & 3) * 4;
                    int xx = r - 1;
                    aR[j] = ((unsigned)yy < 128u && (unsigned)xx < 128u)
                                ? *(const uint4*)&Abf[(size_t)(((b << 7) + yy) * 128 + xx) * 128 +
                                                      icp0 + kq]
                                : z4;
                }
            }
#pragma unroll
            for (int j = 0; j < 6; j++) {
                int s = tid + 256 * j;
                int tapl = s >> 9, st2 = s & 511;
                int kb = st2 >> 5, nq = (st2 & 31) * 4;
                bR[j] = *(const uint4*)&Wp[(size_t)((dyi * 3 + tapl) * 128 + icp0 + kb) * 256 +
                                           nc0 + nq];
            }
        }
        uint32_t aB0 = aBase + cur * (HA_ASTG * 4);
        const uint32_t* Bst = smB + cur * HA_BSTG;
#pragma unroll
        for (int dxi = 0; dxi < 3; dxi++) {
            const uint32_t* Bc = Bst + dxi * 2176;
            uint32_t aBd = aB0 + dxi * 80;
#pragma unroll
            for (int ks = 0; ks < 2; ks++) {
                int kpb = ks * 8;
                uint32_t bf[4][2];
#pragma unroll
                for (int ni = 0; ni < 4; ni++) {
                    int n = wn + ni * 8 + gid;
                    bf[ni][0] = Bc[(kpb + tig) * 136 + n];
                    bf[ni][1] = Bc[(kpb + tig + 4) * 136 + n];
                }
#pragma unroll
                for (int mi = 0; mi < 4; mi++) {
                    uint32_t a[4];
                    ldsm4(a[0], a[1], a[2], a[3], aBd + mi * 1280 + ks * 32);
#pragma unroll
                    for (int ni = 0; ni < 4; ni++) mma_bf16(acc[mi][ni], a, bf[ni]);
                }
            }
        }
        if (st + 1 < 24) {
            int nxt = cur ^ 1;
#pragma unroll
            for (int j = 0; j < 3; j++) {
                int s = tid + 256 * j;
                if (j < 2 || tid < 8)
                    *(uint4*)&smA[nxt * HA_ASTG + (s >> 2) * 20 + (s & 3) * 4] = aR[j];
            }
#pragma unroll
            for (int j = 0; j < 6; j++) {
                int s = tid + 256 * j;
                int tapl = s >> 9, st2 = s & 511;
                *(uint4*)&smB[nxt * HA_BSTG + tapl * 2176 + (st2 >> 5) * 136 +
                              (st2 & 31) * 4] = bR[j];
            }
            __syncthreads();
        }
    }
#pragma unroll
    for (int mi = 0; mi < 4; mi++) {
        int r = m0 + wm + mi * 16 + gid;
#pragma unroll
        for (int ni = 0; ni < 4; ni++) {
            int cb = nc0 + wn + ni * 8 + tig * 2;
            float b0 = bias[cb], b1 = bias[cb + 1];
            CoutH[(size_t)r * 128 + (cb >> 1)] = packh(acc[mi][ni][0] + b0, acc[mi][ni][1] + b1);
            CoutH[(size_t)(r + 8) * 128 + (cb >> 1)] =
                packh(acc[mi][ni][2] + b0, acc[mi][ni][3] + b1);
        }
    }
}

// ---------------- slice logits + softmax over G=64 ----------------
__global__ void slice_softmax_kernel(const uint32_t* __restrict__ xmidh,
                                     const float* __restrict__ sw_w,
                                     const float* __restrict__ sw_b,
                                     const float* __restrict__ temp) {
    int row = blockIdx.x;
    int b = row >> 14;
    int n = row & (Nn - 1);
    int tid = threadIdx.x;  // 512
    __shared__ float sx[256];
    __shared__ float wred[16];
    if (tid < 128) {
        __half2 v = *(const __half2*)&xmidh[(size_t)row * 128 + tid];
        sx[2 * tid] = __low2float(v);
        sx[2 * tid + 1] = __high2float(v);
    }
    __syncthreads();
    int h = tid >> 6, g = tid & 63;
    const float* xh = sx + h * 32;
    float acc = sw_b[g];
#pragma unroll
    for (int d = 0; d < 32; d++) acc += xh[d] * sw_w[d * 64 + g];
    float tp = fminf(fmaxf(temp[h], 0.1f), 5.0f);
    acc /= tp;
    int wid = tid >> 5, lane = tid & 31;
    float m = warpMax(acc);
    if (lane == 0) wred[wid] = m;
    __syncthreads();
    m = fmaxf(wred[h * 2], wred[h * 2 + 1]);
    float e = expf(acc - m);
    __syncthreads();
    float s = warpSum(e);
    if (lane == 0) wred[wid] = s;
    __syncthreads();
    s = wred[h * 2] + wred[h * 2 + 1];
    g_swh[((size_t)(b * HEADS + h) * Nn + n) * Gg + g] = __float2half(e / s);
}

__global__ void zero_stats_kernel() {
    int i = blockIdx.x * 256 + threadIdx.x;
    if (i < Bsz * HEADS * Gg * DHd) g_st[i] = 0.f;
    if (i < Bsz * HEADS * Gg) g_norm[i] = 0.f;
}

// ===== st via fp16 mma: st[64g][32d] += sw^T @ fxmid ; norm[g] += col-sum ====
__global__ __launch_bounds__(256)
void st_mma_kernel() {
    __shared__ uint32_t Ssw[128][36];
    __shared__ uint32_t Sfm[128][20];
    int bh = blockIdx.x;
    int split = blockIdx.y;
    int b = bh >> 3, h = bh & 7;
    int tid = threadIdx.x;
    int wid = tid >> 5, lane = tid & 31;
    int gseg = (wid & 3) * 16;
    int kseg = (wid >> 2) * 64;

    const uint32_t* swp = (const uint32_t*)g_swh + ((size_t)bh * Nn + split * 1024) * 32;
    const uint32_t* fm = g_fxmidh + (size_t)(b * Nn + split * 1024) * 128 + h * 16;

    uint32_t swB = (uint32_t)__cvta_generic_to_shared(&Ssw[0][0]);
    uint32_t fmB = (uint32_t)__cvta_generic_to_shared(&Sfm[0][0]);
    int aRow = ((lane >> 4) & 1) * 8 + (lane & 7);
    uint32_t aOff = swB + (uint32_t)(((gseg + ((lane >> 3) & 1) * 8) >> 1) * 4);
    int bRow = ((lane >> 3) & 1) * 8 + (lane & 7);
    uint32_t bOff = fmB + (uint32_t)((((lane >> 4) & 1) * 8 >> 1) * 4);

    float acc[4][4];
#pragma unroll
    for (int ni = 0; ni < 4; ni++)
#pragma unroll
        for (int q = 0; q < 4; q++) acc[ni][q] = 0.f;
    float2 nacc = make_float2(0.f, 0.f);
    int ng2 = tid & 31, nr0 = (tid >> 5) * 16;

    for (int ck = 0; ck < 8; ck++) {
        __syncthreads();
#pragma unroll
        for (int j = 0; j < 4; j++) {
            int s = tid + 256 * j;
            int r = s >> 3, c = (s & 7) * 4;
            *(uint4*)&Ssw[r][c] = *(const uint4*)&swp[(size_t)(ck * 128 + r) * 32 + c];
        }
#pragma unroll
        for (int j = 0; j < 2; j++) {
            int s = tid + 256 * j;
            int r = s >> 2, c = (s & 3) * 4;
            *(uint4*)&Sfm[r][c] = *(const uint4*)&fm[(size_t)(ck * 128 + r) * 128 + c];
        }
        __syncthreads();
#pragma unroll
        for (int r = 0; r < 16; r++) {
            __half2 v = *(__half2*)&Ssw[nr0 + r][ng2];
            nacc.x += __low2float(v);
            nacc.y += __high2float(v);
        }
#pragma unroll
        for (int ks = 0; ks < 4; ks++) {
            int nk = kseg + ks * 16;
            uint32_t a[4];
            ldsm4t(a[0], a[1], a[2], a[3], aOff + (uint32_t)((nk + aRow) * 144));
            uint32_t b0[4], b1[4];
            ldsm4t(b0[0], b0[1], b0[2], b0[3], bOff + (uint32_t)((nk + bRow) * 80));
            ldsm4t(b1[0], b1[1], b1[2], b1[3], bOff + (uint32_t)((nk + bRow) * 80 + 32));
            {
                uint32_t bf[2];
                bf[0] = b0[0]; bf[1] = b0[1];
                mma_f16(acc[0], a, bf);
                bf[0] = b0[2]; bf[1] = b0[3];
                mma_f16(acc[1], a, bf);
                bf[0] = b1[0]; bf[1] = b1[1];
                mma_f16(acc[2], a, bf);
                bf[0] = b1[2]; bf[1] = b1[3];
                mma_f16(acc[3], a, bf);
            }
        }
    }
    float* stp = g_st + (size_t)bh * 2048;
    int grow = gseg + (lane >> 2);
#pragma unroll
    for (int ni = 0; ni < 4; ni++) {
        int dcol = ni * 8 + (lane & 3) * 2;
        atomicAdd(&stp[grow * 32 + dcol], acc[ni][0]);
        atomicAdd(&stp[grow * 32 + dcol + 1], acc[ni][1]);
        atomicAdd(&stp[(grow + 8) * 32 + dcol], acc[ni][2]);
        atomicAdd(&stp[(grow + 8) * 32 + dcol + 1], acc[ni][3]);
    }
    atomicAdd(&g_norm[bh * 64 + 2 * ng2], nacc.x);
    atomicAdd(&g_norm[bh * 64 + 2 * ng2 + 1], nacc.y);
}

// normalize st, q/k/v, 64x64 attention; write half2-packed ot (g-pairs)
__global__ void qkv_attn_kernel(const float* __restrict__ wq,
                                const float* __restrict__ wk,
                                const float* __restrict__ wv) {
    int bh = blockIdx.x;
    int tid = threadIdx.x;  // 256
    __shared__ float st_s[2048], q_s[2048], k_s[2048], s_s[4096];
    for (int i = tid; i < 2048; i += 256) {
        int g = i >> 5;
        st_s[i] = g_st[bh * 2048 + i] / (g_norm[bh * 64 + g] + 1e-5f);
    }
    __syncthreads();
    for (int i = tid; i < 2048; i += 256) {
        int g = i >> 5, d = i & 31;
        float aq = 0.f, ak = 0.f;
#pragma unroll
        for (int c = 0; c < 32; c++) {
            float s = st_s[g * 32 + c];
            aq += s * wq[c * 32 + d];
            ak += s * wk[c * 32 + d];
        }
        q_s[i] = aq;
        k_s[i] = ak;
    }
    __syncthreads();
    const float scale = 0.17677669529663687f;
    for (int i = tid; i < 4096; i += 256) {
        int g = i >> 6, j = i & 63;
        float a = 0.f;
#pragma unroll
        for (int d = 0; d < 32; d++) a += q_s[g * 32 + d] * k_s[j * 32 + d];
        s_s[i] = a * scale;
    }
    __syncthreads();
    if (tid < 64) {
        float m = -1e30f;
        for (int j = 0; j < 64; j++) m = fmaxf(m, s_s[tid * 64 + j]);
        float sum = 0.f;
        for (int j = 0; j < 64; j++) {
            float e = expf(s_s[tid * 64 + j] - m);
            s_s[tid * 64 + j] = e;
            sum += e;
        }
        float inv = 1.f / sum;
        for (int j = 0; j < 64; j++) s_s[tid * 64 + j] *= inv;
    }
    __syncthreads();
    for (int i = tid; i < 2048; i += 256) {
        int g = i >> 5, d = i & 31;
        float a = 0.f;
#pragma unroll
        for (int j = 0; j < 64; j++) a += s_s[g * 64 + j] * st_s[j * 32 + d];
        q_s[i] = a;
    }
    __syncthreads();
    for (int i = tid; i < 2048; i += 256) {
        int g = i >> 5, d = i & 31;
        float a = 0.f;
#pragma unroll
        for (int c = 0; c < 32; c++) a += q_s[g * 32 + c] * wv[c * 32 + d];
        k_s[i] = a;
    }
    __syncthreads();
    for (int i = tid; i < 1024; i += 256) {
        int gp = i >> 5, d = i & 31;
        g_otp[bh * 1024 + i] = packh(k_s[(2 * gp) * 32 + d], k_s[(2 * gp + 1) * 32 + d]);
    }
}

// ============ deslice via fp16 mma: outx[128n x 32d] = sw[128n x 64g] @ ot ===
__global__ __launch_bounds__(256, 2)
void deslice_mma_kernel() {
    __shared__ uint32_t As[128][36];
    __shared__ uint32_t Bp[32][33];
    int n0 = blockIdx.x * 128;
    int bh = blockIdx.y;
    int b = bh >> 3, h = bh & 7;
    int tid = threadIdx.x;
    int wid = tid >> 5, lane = tid & 31;
    int wm = wid * 16;
    int gid = lane >> 2, tig = lane & 3;

    const uint32_t* swp = (const uint32_t*)g_swh + ((size_t)bh * Nn + n0) * 32;
#pragma unroll
    for (int j = 0; j < 4; j++) {
        int s = tid + 256 * j;
        int r = s >> 3, c = (s & 7) * 4;
        *(uint4*)&As[r][c] = *(const uint4*)&swp[(size_t)r * 32 + c];
    }
#pragma unroll
    for (int j = 0; j < 4; j++) {
        int s = tid + 256 * j;
        Bp[s >> 5][s & 31] = g_otp[bh * 1024 + s];
    }
    __syncthreads();

    uint32_t smemA = (uint32_t)__cvta_generic_to_shared(&As[0][0]);
    int arow = wm + (lane & 7) + ((lane >> 3) & 1) * 8;
    uint32_t aBase = smemA + (uint32_t)((arow * 36 + ((lane >> 4) << 2)) * 4);

    float acc[4][4];
#pragma unroll
    for (int ni = 0; ni < 4; ni++)
#pragma unroll
        for (int q = 0; q < 4; q++) acc[ni][q] = 0.f;

#pragma unroll
    for (int ks = 0; ks < 4; ks++) {
        uint32_t a[4];
        ldsm4(a[0], a[1], a[2], a[3], aBase + ks * 32);
#pragma unroll
        for (int ni = 0; ni < 4; ni++) {
            uint32_t bfr[2];
            bfr[0] = Bp[ks * 8 + tig][ni * 8 + gid];
            bfr[1] = Bp[ks * 8 + tig + 4][ni * 8 + gid];
            mma_f16(acc[ni], a, bfr);
        }
    }
    int r = n0 + wm + gid;
#pragma unroll
    for (int ni = 0; ni < 4; ni++) {
        int dp = ni * 4 + tig;
        g_outxbf[((size_t)b * Nn + r) * 128 + h * 16 + dp] = packbf(acc[ni][0], acc[ni][1]);
        g_outxbf[((size_t)b * Nn + r + 8) * 128 + h * 16 + dp] = packbf(acc[ni][2], acc[ni][3]);
    }
}

// ---------------- driver ----------------
extern "C" void kernel_launch(void* const* d_in, const int* in_sizes, int n_in,
                              void* d_out, int out_size) {
    const float* fx_in  = (const float*)d_in[0];
    const float* ln1_w  = (const float*)d_in[1];
    const float* ln1_b  = (const float*)d_in[2];
    const float* convx_w  = (const float*)d_in[3];
    const float* convx_b  = (const float*)d_in[4];
    const float* convfx_w = (const float*)d_in[5];
    const float* convfx_b = (const float*)d_in[6];
    const float* slice_w  = (const float*)d_in[7];
    const float* slice_b  = (const float*)d_in[8];
    const float* temperature = (const float*)d_in[9];
    const float* wq = (const float*)d_in[10];
    const float* wk = (const float*)d_in[11];
    const float* wv = (const float*)d_in[12];
    const float* wo = (const float*)d_in[13];
    const float* bo = (const float*)d_in[14];
    const float* ln2_w = (const float*)d_in[15];
    const float* ln2_b = (const float*)d_in[16];
    const float* w1 = (const float*)d_in[17];
    const float* b1 = (const float*)d_in[18];
    const float* w2 = (const float*)d_in[19];
    const float* b2 = (const float*)d_in[20];
    const float* ln3_w = (const float*)d_in[21];
    const float* ln3_b = (const float*)d_in[22];
    const float* w_out = (const float*)d_in[23];
    const float* b_out = (const float*)d_in[24];

    float* p_fx;
    uint32_t *p_lnbf, *p_xmidh, *p_fxmidh, *p_outxbf, *p_hidbf, *p_wpk;
    cudaGetSymbolAddress((void**)&p_fx, g_fx);
    cudaGetSymbolAddress((void**)&p_lnbf, g_lnbf);
    cudaGetSymbolAddress((void**)&p_xmidh, g_xmidh);
    cudaGetSymbolAddress((void**)&p_fxmidh, g_fxmidh);
    cudaGetSymbolAddress((void**)&p_outxbf, g_outxbf);
    cudaGetSymbolAddress((void**)&p_hidbf, g_hidbf);
    cudaGetSymbolAddress((void**)&p_wpk, g_wpk);

    cudaFuncSetAttribute(conv_bf16_kernel, cudaFuncAttributeMaxDynamicSharedMemorySize,
                         HA_SMEM);

    pack_kernel<<<2048, 256>>>(convx_w, p_wpk + WPK_CONVX, 1152, 256, Lnum,
                               (size_t)2304 * 256, WPK_LAYER);
    pack_kernel<<<2048, 256>>>(convfx_w, p_wpk + WPK_CONVFX, 1152, 256, Lnum,
                               (size_t)2304 * 256, WPK_LAYER);
    pack_kernel<<<256, 256>>>(wo, p_wpk + WPK_WO, 128, 256, Lnum,
                              (size_t)256 * 256, WPK_LAYER);
    pack_kernel<<<1024, 256>>>(w1, p_wpk + WPK_W1, 128, 1024, Lnum,
                               (size_t)256 * 1024, WPK_LAYER);
    pack_kernel<<<1024, 256>>>(w2, p_wpk + WPK_W2, 512, 256, Lnum,
                               (size_t)1024 * 256, WPK_LAYER);

    copy_in_kernel<<<ROWS * Cc / 256, 256>>>(fx_in);

    for (int i = 0; i < Lnum; i++) {
        const uint32_t* wl = p_wpk + (size_t)i * WPK_LAYER;
        ln_kernel<<<ROWS, 256>>>(p_fx, p_lnbf, ln1_w + i * Cc, ln1_b + i * Cc);
        dim3 cg(ROWS / 128, 2);
        conv_bf16_kernel<<<cg, 256, HA_SMEM>>>(p_lnbf, wl + WPK_CONVX, convx_b + i * INNERc,
                                               p_xmidh);
        conv_bf16_kernel<<<cg, 256, HA_SMEM>>>(p_lnbf, wl + WPK_CONVFX, convfx_b + i * INNERc,
                                               p_fxmidh);
        slice_softmax_kernel<<<ROWS, 512>>>(p_xmidh, slice_w + i * DHd * Gg,
                                            slice_b + i * Gg, temperature + i * HEADS);
        zero_stats_kernel<<<(Bsz * HEADS * Gg * DHd + 255) / 256, 256>>>();
        st_mma_kernel<<<dim3(Bsz * HEADS, 16), 256>>>();
        qkv_attn_kernel<<<Bsz * HEADS, 256>>>(wq + i * DHd * DHd, wk + i * DHd * DHd,
                                              wv + i * DHd * DHd);
        deslice_mma_kernel<<<dim3(Nn / 128, Bsz * HEADS), 256>>>();
        gemm_bf16_kernel<false, true, false><<<dim3(ROWS / 128, 2), 256>>>(
            p_outxbf, wl + WPK_WO, bo + i * Cc, p_fx, p_fx, nullptr, 128, Cc);
        ln_kernel<<<ROWS, 256>>>(p_fx, p_lnbf, ln2_w + i * Cc, ln2_b + i * Cc);
        gemm_bf16_kernel<true, false, true><<<dim3(ROWS / 128, HIDc / 128), 256>>>(
            p_lnbf, wl + WPK_W1, b1 + i * HIDc, nullptr, nullptr, p_hidbf, 128, HIDc);
        gemm_bf16_kernel<false, true, false><<<dim3(ROWS / 128, 2), 256>>>(
            p_hidbf, wl + WPK_W2, b2 + i * Cc, p_fx, p_fx, nullptr, 512, Cc);
    }

    ln_head_kernel<<<ROWS / 8, 256>>>(p_fx, ln3_w, ln3_b, w_out, b_out, (float*)d_out);
}

// round 17
// speedup vs baseline: 1.6776x; 1.0660x over previous
#include <cuda_runtime.h>
#include <cuda_fp16.h>
#include <stdint.h>
#include <math.h>

#define DEV_INLINE __device__ __forceinline__

constexpr int Bsz = 4, Cc = 256, Hh = 128, Ww = 128, Nn = Hh * Ww;
constexpr int HEADS = 8, DHd = 32, Gg = 64, INNERc = 256, HIDc = 1024;
constexpr int Lnum = 4, OUTc = 4;
constexpr int ROWS = Bsz * Nn;  // 65536

// packed-weight layout (u32 = bf16x2 k-pairs, k-major), per layer offsets
constexpr int WPK_CONVX = 0;                       // Kp=1152, N=256
constexpr int WPK_CONVFX = 1152 * 256;
constexpr int WPK_WO = 2 * 1152 * 256;             // Kp=128, N=256
constexpr int WPK_W1 = WPK_WO + 128 * 256;         // Kp=128, N=1024
constexpr int WPK_W2 = WPK_W1 + 128 * 1024;        // Kp=512, N=256
constexpr int WPK_LAYER = WPK_W2 + 512 * 256;

// ---------------- scratch (device globals; no runtime alloc) ----------------
__device__ float g_fx[ROWS * Cc];
__device__ uint32_t g_lnbf[ROWS * (Cc / 2)];
__device__ uint32_t g_xmidh[ROWS * (INNERc / 2)];
__device__ uint32_t g_fxmidh[ROWS * (INNERc / 2)];
__device__ __half g_swh[(size_t)Bsz * HEADS * Nn * Gg];
__device__ float g_st[Bsz * HEADS * Gg * DHd];
__device__ float g_norm[Bsz * HEADS * Gg];
__device__ uint32_t g_otp[Bsz * HEADS * (Gg / 2) * DHd];
__device__ uint32_t g_outxbf[ROWS * (INNERc / 2)];
__device__ uint32_t g_hidbf[ROWS * (HIDc / 2)];
__device__ uint32_t g_wpk[Lnum * WPK_LAYER];

// ---------------- helpers ----------------
DEV_INLINE float warpSum(float v) {
#pragma unroll
    for (int o = 16; o; o >>= 1) v += __shfl_xor_sync(0xffffffffu, v, o);
    return v;
}
DEV_INLINE float warpMax(float v) {
#pragma unroll
    for (int o = 16; o; o >>= 1) v = fmaxf(v, __shfl_xor_sync(0xffffffffu, v, o));
    return v;
}
DEV_INLINE uint32_t packbf(float lo, float hi) {
    uint32_t r;
    asm("cvt.rn.bf16x2.f32 %0, %1, %2;" : "=r"(r) : "f"(hi), "f"(lo));
    return r;
}
DEV_INLINE uint32_t packh(float lo, float hi) {
    uint32_t r;
    asm("cvt.rn.f16x2.f32 %0, %1, %2;" : "=r"(r) : "f"(hi), "f"(lo));
    return r;
}
DEV_INLINE void mma_bf16(float c[4], const uint32_t a[4], const uint32_t b[2]) {
    asm volatile(
        "mma.sync.aligned.m16n8k16.row.col.f32.bf16.bf16.f32 "
        "{%0,%1,%2,%3}, {%4,%5,%6,%7}, {%8,%9}, {%0,%1,%2,%3};"
        : "+f"(c[0]), "+f"(c[1]), "+f"(c[2]), "+f"(c[3])
        : "r"(a[0]), "r"(a[1]), "r"(a[2]), "r"(a[3]), "r"(b[0]), "r"(b[1]));
}
DEV_INLINE void mma_f16(float c[4], const uint32_t a[4], const uint32_t b[2]) {
    asm volatile(
        "mma.sync.aligned.m16n8k16.row.col.f32.f16.f16.f32 "
        "{%0,%1,%2,%3}, {%4,%5,%6,%7}, {%8,%9}, {%0,%1,%2,%3};"
        : "+f"(c[0]), "+f"(c[1]), "+f"(c[2]), "+f"(c[3])
        : "r"(a[0]), "r"(a[1]), "r"(a[2]), "r"(a[3]), "r"(b[0]), "r"(b[1]));
}
DEV_INLINE void ldsm4(uint32_t& r0, uint32_t& r1, uint32_t& r2, uint32_t& r3,
                      uint32_t addr) {
    asm volatile("ldmatrix.sync.aligned.m8n8.x4.shared.b16 {%0,%1,%2,%3}, [%4];"
                 : "=r"(r0), "=r"(r1), "=r"(r2), "=r"(r3)
                 : "r"(addr));
}
DEV_INLINE void ldsm4t(uint32_t& r0, uint32_t& r1, uint32_t& r2, uint32_t& r3,
                       uint32_t addr) {
    asm volatile("ldmatrix.sync.aligned.m8n8.x4.trans.shared.b16 {%0,%1,%2,%3}, [%4];"
                 : "=r"(r0), "=r"(r1), "=r"(r2), "=r"(r3)
                 : "r"(addr));
}

// ---------------- copy input ----------------
__global__ void copy_in_kernel(const float* __restrict__ src) {
    int i = blockIdx.x * 256 + threadIdx.x;
    g_fx[i] = src[i];
}

// ---------------- weight pre-pack: k-major bf16 k-pair packing --------------
__global__ void pack_kernel(const float* __restrict__ src, uint32_t* __restrict__ dst,
                            int Kp, int N, int L, size_t sstride, size_t dstride) {
    int total = L * Kp * N;
    for (int idx = blockIdx.x * blockDim.x + threadIdx.x; idx < total;
         idx += gridDim.x * blockDim.x) {
        int l = idx / (Kp * N);
        int r = idx - l * (Kp * N);
        int kp = r / N, n = r - kp * N;
        float lo = src[l * sstride + (size_t)(2 * kp) * N + n];
        float hi = src[l * sstride + (size_t)(2 * kp + 1) * N + n];
        dst[l * dstride + (size_t)kp * N + n] = packbf(lo, hi);
    }
}

// ---------------- warp-per-row layernorm (8 rows per 256-thread CTA) --------
__global__ void ln8_kernel(const float* __restrict__ in, uint32_t* __restrict__ outb,
                           const float* __restrict__ w, const float* __restrict__ b) {
    int warp = threadIdx.x >> 5, lane = threadIdx.x & 31;
    int row = blockIdx.x * 8 + warp;
    int c0 = lane * 8;
    const float* rp = in + (size_t)row * Cc + c0;
    float v[8];
    *(float4*)(v) = *(const float4*)rp;
    *(float4*)(v + 4) = *(const float4*)(rp + 4);
    float s = v[0] + v[1] + v[2] + v[3] + v[4] + v[5] + v[6] + v[7];
    float m = warpSum(s) * (1.f / Cc);
    float s2 = 0.f;
#pragma unroll
    for (int j = 0; j < 8; j++) {
        v[j] -= m;
        s2 += v[j] * v[j];
    }
    float rstd = rsqrtf(warpSum(s2) * (1.f / Cc) + 1e-5f);
    float wv[8], bv[8];
    *(float4*)(wv) = *(const float4*)(w + c0);
    *(float4*)(wv + 4) = *(const float4*)(w + c0 + 4);
    *(float4*)(bv) = *(const float4*)(b + c0);
    *(float4*)(bv + 4) = *(const float4*)(b + c0 + 4);
    uint32_t o[4];
#pragma unroll
    for (int j = 0; j < 4; j++) {
        float lo = v[2 * j] * rstd * wv[2 * j] + bv[2 * j];
        float hi = v[2 * j + 1] * rstd * wv[2 * j + 1] + bv[2 * j + 1];
        o[j] = packbf(lo, hi);
    }
    *(uint4*)&outb[(size_t)row * (Cc / 2) + lane * 4] = make_uint4(o[0], o[1], o[2], o[3]);
}

// ---------------- fused ln3 + head: out = ln(fx)@w_out + b_out --------------
__global__ void ln_head_kernel(const float* __restrict__ in, const float* __restrict__ lw,
                               const float* __restrict__ lb, const float* __restrict__ wout,
                               const float* __restrict__ bout, float* __restrict__ out) {
    int warp = threadIdx.x >> 5, lane = threadIdx.x & 31;
    int row = blockIdx.x * 8 + warp;
    int c0 = lane * 8;
    const float* rp = in + (size_t)row * Cc + c0;
    float v[8];
    *(float4*)(v) = *(const float4*)rp;
    *(float4*)(v + 4) = *(const float4*)(rp + 4);
    float s = v[0] + v[1] + v[2] + v[3] + v[4] + v[5] + v[6] + v[7];
    float m = warpSum(s) * (1.f / Cc);
    float s2 = 0.f;
#pragma unroll
    for (int j = 0; j < 8; j++) {
        v[j] -= m;
        s2 += v[j] * v[j];
    }
    float rstd = rsqrtf(warpSum(s2) * (1.f / Cc) + 1e-5f);
    float wv[8], bv[8];
    *(float4*)(wv) = *(const float4*)(lw + c0);
    *(float4*)(wv + 4) = *(const float4*)(lw + c0 + 4);
    *(float4*)(bv) = *(const float4*)(lb + c0);
    *(float4*)(bv + 4) = *(const float4*)(lb + c0 + 4);
    float o[8];
#pragma unroll
    for (int j = 0; j < 8; j++) o[j] = v[j] * rstd * wv[j] + bv[j];
    float p[4] = {0.f, 0.f, 0.f, 0.f};
#pragma unroll
    for (int j = 0; j < 8; j++) {
        float4 wr = *(const float4*)&wout[(c0 + j) * 4];
        p[0] += o[j] * wr.x;
        p[1] += o[j] * wr.y;
        p[2] += o[j] * wr.z;
        p[3] += o[j] * wr.w;
    }
#pragma unroll
    for (int oc = 0; oc < 4; oc++) p[oc] = warpSum(p[oc]);
    if (lane == 0) {
        float4 bo4 = *(const float4*)bout;
        *(float4*)&out[(size_t)row * 4] =
            make_float4(p[0] + bo4.x, p[1] + bo4.y, p[2] + bo4.z, p[3] + bo4.w);
    }
}

// ===== bf16 GEMM (R8): dbl-buffered smem, register-staged LDG, 1 sync/chunk ==
constexpr int ABUF = 128 * 20;  // u32 per A stage

template <bool GELU, bool RES, bool BFOUT>
__global__ __launch_bounds__(256, 2)
void gemm_bf16_kernel(const uint32_t* __restrict__ A, const uint32_t* __restrict__ Bw,
                      const float* __restrict__ bias, const float* __restrict__ resid,
                      float* __restrict__ CoutF, uint32_t* __restrict__ CoutB,
                      int Kp, int Nc) {
    __shared__ uint32_t As2[2][128][20];
    __shared__ uint32_t Bs2[2][16][136];
    int tid = threadIdx.x;
    int m0 = blockIdx.x * 128, nc0 = blockIdx.y * 128;
    int wid = tid >> 5, lane = tid & 31;
    int wm = (wid >> 2) * 64, wn = (wid & 3) * 32;
    int gid = lane >> 2, tig = lane & 3;

    uint32_t smemA = (uint32_t)__cvta_generic_to_shared(&As2[0][0][0]);
    int arow = wm + (lane & 7) + ((lane >> 3) & 1) * 8;
    uint32_t aBase = smemA + (uint32_t)((arow * 20 + ((lane >> 4) << 2)) * 4);

    float acc[4][4][4];
#pragma unroll
    for (int mi = 0; mi < 4; mi++)
#pragma unroll
        for (int ni = 0; ni < 4; ni++)
#pragma unroll
            for (int q = 0; q < 4; q++) acc[mi][ni][q] = 0.f;

    uint4 aP[2], bP[2];
#pragma unroll
    for (int j = 0; j < 2; j++) {
        int s = tid + 256 * j;
        aP[j] = *(const uint4*)&A[(size_t)(m0 + (s >> 2)) * Kp + (s & 3) * 4];
        bP[j] = *(const uint4*)&Bw[(size_t)(s >> 5) * Nc + nc0 + (s & 31) * 4];
    }
#pragma unroll
    for (int j = 0; j < 2; j++) {
        int s = tid + 256 * j;
        *(uint4*)&As2[0][s >> 2][(s & 3) * 4] = aP[j];
        *(uint4*)&Bs2[0][s >> 5][(s & 31) * 4] = bP[j];
    }
    __syncthreads();

    int nch = Kp >> 4;
    for (int ch = 0; ch < nch; ch++) {
        int cur = ch & 1;
        if (ch + 1 < nch) {
            int kc = (ch + 1) * 16;
#pragma unroll
            for (int j = 0; j < 2; j++) {
                int s = tid + 256 * j;
                aP[j] = *(const uint4*)&A[(size_t)(m0 + (s >> 2)) * Kp + kc + (s & 3) * 4];
                bP[j] = *(const uint4*)&Bw[(size_t)(kc + (s >> 5)) * Nc + nc0 + (s & 31) * 4];
            }
        }
        uint32_t aB = aBase + cur * (ABUF * 4);
#pragma unroll
        for (int ks = 0; ks < 2; ks++) {
            int kpb = ks * 8;
            uint32_t bf[4][2];
#pragma unroll
            for (int ni = 0; ni < 4; ni++) {
                int n = wn + ni * 8 + gid;
                bf[ni][0] = Bs2[cur][kpb + tig][n];
                bf[ni][1] = Bs2[cur][kpb + tig + 4][n];
            }
#pragma unroll
            for (int mi = 0; mi < 4; mi++) {
                uint32_t a[4];
                ldsm4(a[0], a[1], a[2], a[3], aB + mi * 1280 + ks * 32);
#pragma unroll
                for (int ni = 0; ni < 4; ni++) mma_bf16(acc[mi][ni], a, bf[ni]);
            }
        }
        if (ch + 1 < nch) {
            int nxt = cur ^ 1;
#pragma unroll
            for (int j = 0; j < 2; j++) {
                int s = tid + 256 * j;
                *(uint4*)&As2[nxt][s >> 2][(s & 3) * 4] = aP[j];
                *(uint4*)&Bs2[nxt][s >> 5][(s & 31) * 4] = bP[j];
            }
            __syncthreads();
        }
    }
#pragma unroll
    for (int mi = 0; mi < 4; mi++) {
        int r = m0 + wm + mi * 16 + gid;
#pragma unroll
        for (int ni = 0; ni < 4; ni++) {
            int cb = nc0 + wn + ni * 8 + tig * 2;
            float b0 = bias[cb], b1 = bias[cb + 1];
            float v0 = acc[mi][ni][0] + b0, v1 = acc[mi][ni][1] + b1;
            float v2 = acc[mi][ni][2] + b0, v3 = acc[mi][ni][3] + b1;
            if (GELU) {
                v0 = 0.5f * v0 * (1.f + erff(v0 * 0.70710678118654752f));
                v1 = 0.5f * v1 * (1.f + erff(v1 * 0.70710678118654752f));
                v2 = 0.5f * v2 * (1.f + erff(v2 * 0.70710678118654752f));
                v3 = 0.5f * v3 * (1.f + erff(v3 * 0.70710678118654752f));
            }
            if (RES) {
                v0 += resid[(size_t)r * Nc + cb];
                v1 += resid[(size_t)r * Nc + cb + 1];
                v2 += resid[(size_t)(r + 8) * Nc + cb];
                v3 += resid[(size_t)(r + 8) * Nc + cb + 1];
            }
            if (BFOUT) {
                CoutB[(size_t)r * (Nc / 2) + (cb >> 1)] = packbf(v0, v1);
                CoutB[(size_t)(r + 8) * (Nc / 2) + (cb >> 1)] = packbf(v2, v3);
            } else {
                *(float2*)&CoutF[(size_t)r * Nc + cb] = make_float2(v0, v1);
                *(float2*)&CoutF[(size_t)(r + 8) * Nc + cb] = make_float2(v2, v3);
            }
        }
    }
}

// ===== bf16 conv 3x3 implicit GEMM with A-halo reuse (R16) ===================
constexpr int HA_ASTG = 130 * 20;        // u32 per A stage
constexpr int HA_BSTG = 3 * 16 * 136;    // u32 per B stage
constexpr int HA_SMEM = 2 * (HA_ASTG + HA_BSTG) * 4;  // 73024 B

__global__ __launch_bounds__(256, 2)
void conv_bf16_kernel(const uint32_t* __restrict__ Abf, const uint32_t* __restrict__ Wp,
                      const float* __restrict__ bias, uint32_t* __restrict__ CoutH) {
    extern __shared__ uint32_t sm[];
    uint32_t* smA = sm;                  // [2][130][20]
    uint32_t* smB = sm + 2 * HA_ASTG;    // [2][3][16][136]
    int tid = threadIdx.x;
    int m0 = blockIdx.x * 128, nc0 = blockIdx.y * 128;
    int b = blockIdx.x >> 7;
    int y = blockIdx.x & 127;
    int wid = tid >> 5, lane = tid & 31;
    int wm = (wid >> 2) * 64, wn = (wid & 3) * 32;
    int gid = lane >> 2, tig = lane & 3;

    uint32_t smemA = (uint32_t)__cvta_generic_to_shared(smA);
    int arow = wm + (lane & 7) + ((lane >> 3) & 1) * 8;
    uint32_t aBase = smemA + (uint32_t)((arow * 20 + ((lane >> 4) << 2)) * 4);

    float acc[4][4][4];
#pragma unroll
    for (int mi = 0; mi < 4; mi++)
#pragma unroll
        for (int ni = 0; ni < 4; ni++)
#pragma unroll
            for (int q = 0; q < 4; q++) acc[mi][ni][q] = 0.f;

    uint4 aR[3], bR[6];
    const uint4 z4 = make_uint4(0, 0, 0, 0);

    // prologue: stage 0 = (dy=-1, icp0=0)
    {
        int yy = y - 1;
#pragma unroll
        for (int j = 0; j < 3; j++) {
            int s = tid + 256 * j;
            if (j < 2 || tid < 8) {
                int r = s >> 2, kq = (s & 3) * 4;
                int xx = r - 1;
                aR[j] = ((unsigned)yy < 128u && (unsigned)xx < 128u)
                            ? *(const uint4*)&Abf[(size_t)(((b << 7) + yy) * 128 + xx) * 128 + kq]
                            : z4;
            }
        }
#pragma unroll
        for (int j = 0; j < 6; j++) {
            int s = tid + 256 * j;
            int tapl = s >> 9, st2 = s & 511;
            int kb = st2 >> 5, nq = (st2 & 31) * 4;
            bR[j] = *(const uint4*)&Wp[(size_t)(tapl * 128 + kb) * 256 + nc0 + nq];
        }
#pragma unroll
        for (int j = 0; j < 3; j++) {
            int s = tid + 256 * j;
            if (j < 2 || tid < 8)
                *(uint4*)&smA[(s >> 2) * 20 + (s & 3) * 4] = aR[j];
        }
#pragma unroll
        for (int j = 0; j < 6; j++) {
            int s = tid + 256 * j;
            int tapl = s >> 9, st2 = s & 511;
            *(uint4*)&smB[tapl * 2176 + (st2 >> 5) * 136 + (st2 & 31) * 4] = bR[j];
        }
    }
    __syncthreads();

    for (int st = 0; st < 24; st++) {
        int cur = st & 1;
        if (st + 1 < 24) {
            int ns = st + 1;
            int dyi = ns >> 3, icp0 = (ns & 7) * 16;
            int yy = y + dyi - 1;
#pragma unroll
            for (int j = 0; j < 3; j++) {
                int s = tid + 256 * j;
                if (j < 2 || tid < 8) {
                    int r = s >> 2, kq = (s & 3) * 4;
                    int xx = r - 1;
                    aR[j] = ((unsigned)yy < 128u && (unsigned)xx < 128u)
                                ? *(const uint4*)&Abf[(size_t)(((b << 7) + yy) * 128 + xx) * 128 +
                                                      icp0 + kq]
                                : z4;
                }
            }
#pragma unroll
            for (int j = 0; j < 6; j++) {
                int s = tid + 256 * j;
                int tapl = s >> 9, st2 = s & 511;
                int kb = st2 >> 5, nq = (st2 & 31) * 4;
                bR[j] = *(const uint4*)&Wp[(size_t)((dyi * 3 + tapl) * 128 + icp0 + kb) * 256 +
                                           nc0 + nq];
            }
        }
        uint32_t aB0 = aBase + cur * (HA_ASTG * 4);
        const uint32_t* Bst = smB + cur * HA_BSTG;
#pragma unroll
        for (int dxi = 0; dxi < 3; dxi++) {
            const uint32_t* Bc = Bst + dxi * 2176;
            uint32_t aBd = aB0 + dxi * 80;
#pragma unroll
            for (int ks = 0; ks < 2; ks++) {
                int kpb = ks * 8;
                uint32_t bf[4][2];
#pragma unroll
                for (int ni = 0; ni < 4; ni++) {
                    int n = wn + ni * 8 + gid;
                    bf[ni][0] = Bc[(kpb + tig) * 136 + n];
                    bf[ni][1] = Bc[(kpb + tig + 4) * 136 + n];
                }
#pragma unroll
                for (int mi = 0; mi < 4; mi++) {
                    uint32_t a[4];
                    ldsm4(a[0], a[1], a[2], a[3], aBd + mi * 1280 + ks * 32);
#pragma unroll
                    for (int ni = 0; ni < 4; ni++) mma_bf16(acc[mi][ni], a, bf[ni]);
                }
            }
        }
        if (st + 1 < 24) {
            int nxt = cur ^ 1;
#pragma unroll
            for (int j = 0; j < 3; j++) {
                int s = tid + 256 * j;
                if (j < 2 || tid < 8)
                    *(uint4*)&smA[nxt * HA_ASTG + (s >> 2) * 20 + (s & 3) * 4] = aR[j];
            }
#pragma unroll
            for (int j = 0; j < 6; j++) {
                int s = tid + 256 * j;
                int tapl = s >> 9, st2 = s & 511;
                *(uint4*)&smB[nxt * HA_BSTG + tapl * 2176 + (st2 >> 5) * 136 +
                              (st2 & 31) * 4] = bR[j];
            }
            __syncthreads();
        }
    }
#pragma unroll
    for (int mi = 0; mi < 4; mi++) {
        int r = m0 + wm + mi * 16 + gid;
#pragma unroll
        for (int ni = 0; ni < 4; ni++) {
            int cb = nc0 + wn + ni * 8 + tig * 2;
            float b0 = bias[cb], b1 = bias[cb + 1];
            CoutH[(size_t)r * 128 + (cb >> 1)] = packh(acc[mi][ni][0] + b0, acc[mi][ni][1] + b1);
            CoutH[(size_t)(r + 8) * 128 + (cb >> 1)] =
                packh(acc[mi][ni][2] + b0, acc[mi][ni][3] + b1);
        }
    }
}

// ---------------- slice logits + softmax over G=64 ----------------
__global__ void slice_softmax_kernel(const uint32_t* __restrict__ xmidh,
                                     const float* __restrict__ sw_w,
                                     const float* __restrict__ sw_b,
                                     const float* __restrict__ temp) {
    int row = blockIdx.x;
    int b = row >> 14;
    int n = row & (Nn - 1);
    int tid = threadIdx.x;  // 512
    __shared__ float sx[256];
    __shared__ float wred[16];
    if (tid < 128) {
        __half2 v = *(const __half2*)&xmidh[(size_t)row * 128 + tid];
        sx[2 * tid] = __low2float(v);
        sx[2 * tid + 1] = __high2float(v);
    }
    __syncthreads();
    int h = tid >> 6, g = tid & 63;
    const float* xh = sx + h * 32;
    float acc = sw_b[g];
#pragma unroll
    for (int d = 0; d < 32; d++) acc += xh[d] * sw_w[d * 64 + g];
    float tp = fminf(fmaxf(temp[h], 0.1f), 5.0f);
    acc /= tp;
    int wid = tid >> 5, lane = tid & 31;
    float m = warpMax(acc);
    if (lane == 0) wred[wid] = m;
    __syncthreads();
    m = fmaxf(wred[h * 2], wred[h * 2 + 1]);
    float e = expf(acc - m);
    __syncthreads();
    float s = warpSum(e);
    if (lane == 0) wred[wid] = s;
    __syncthreads();
    s = wred[h * 2] + wred[h * 2 + 1];
    g_swh[((size_t)(b * HEADS + h) * Nn + n) * Gg + g] = __float2half(e / s);
}

__global__ void zero_stats_kernel() {
    int i = blockIdx.x * 256 + threadIdx.x;
    if (i < Bsz * HEADS * Gg * DHd) g_st[i] = 0.f;
    if (i < Bsz * HEADS * Gg) g_norm[i] = 0.f;
}

// ===== st via fp16 mma: st[64g][32d] += sw^T @ fxmid ; norm[g] += col-sum ====
__global__ __launch_bounds__(256)
void st_mma_kernel() {
    __shared__ uint32_t Ssw[128][36];
    __shared__ uint32_t Sfm[128][20];
    int bh = blockIdx.x;
    int split = blockIdx.y;
    int b = bh >> 3, h = bh & 7;
    int tid = threadIdx.x;
    int wid = tid >> 5, lane = tid & 31;
    int gseg = (wid & 3) * 16;
    int kseg = (wid >> 2) * 64;

    const uint32_t* swp = (const uint32_t*)g_swh + ((size_t)bh * Nn + split * 1024) * 32;
    const uint32_t* fm = g_fxmidh + (size_t)(b * Nn + split * 1024) * 128 + h * 16;

    uint32_t swB = (uint32_t)__cvta_generic_to_shared(&Ssw[0][0]);
    uint32_t fmB = (uint32_t)__cvta_generic_to_shared(&Sfm[0][0]);
    int aRow = ((lane >> 4) & 1) * 8 + (lane & 7);
    uint32_t aOff = swB + (uint32_t)(((gseg + ((lane >> 3) & 1) * 8) >> 1) * 4);
    int bRow = ((lane >> 3) & 1) * 8 + (lane & 7);
    uint32_t bOff = fmB + (uint32_t)((((lane >> 4) & 1) * 8 >> 1) * 4);

    float acc[4][4];
#pragma unroll
    for (int ni = 0; ni < 4; ni++)
#pragma unroll
        for (int q = 0; q < 4; q++) acc[ni][q] = 0.f;
    float2 nacc = make_float2(0.f, 0.f);
    int ng2 = tid & 31, nr0 = (tid >> 5) * 16;

    for (int ck = 0; ck < 8; ck++) {
        __syncthreads();
#pragma unroll
        for (int j = 0; j < 4; j++) {
            int s = tid + 256 * j;
            int r = s >> 3, c = (s & 7) * 4;
            *(uint4*)&Ssw[r][c] = *(const uint4*)&swp[(size_t)(ck * 128 + r) * 32 + c];
        }
#pragma unroll
        for (int j = 0; j < 2; j++) {
            int s = tid + 256 * j;
            int r = s >> 2, c = (s & 3) * 4;
            *(uint4*)&Sfm[r][c] = *(const uint4*)&fm[(size_t)(ck * 128 + r) * 128 + c];
        }
        __syncthreads();
#pragma unroll
        for (int r = 0; r < 16; r++) {
            __half2 v = *(__half2*)&Ssw[nr0 + r][ng2];
            nacc.x += __low2float(v);
            nacc.y += __high2float(v);
        }
#pragma unroll
        for (int ks = 0; ks < 4; ks++) {
            int nk = kseg + ks * 16;
            uint32_t a[4];
            ldsm4t(a[0], a[1], a[2], a[3], aOff + (uint32_t)((nk + aRow) * 144));
            uint32_t b0[4], b1[4];
            ldsm4t(b0[0], b0[1], b0[2], b0[3], bOff + (uint32_t)((nk + bRow) * 80));
            ldsm4t(b1[0], b1[1], b1[2], b1[3], bOff + (uint32_t)((nk + bRow) * 80 + 32));
            {
                uint32_t bf[2];
                bf[0] = b0[0]; bf[1] = b0[1];
                mma_f16(acc[0], a, bf);
                bf[0] = b0[2]; bf[1] = b0[3];
                mma_f16(acc[1], a, bf);
                bf[0] = b1[0]; bf[1] = b1[1];
                mma_f16(acc[2], a, bf);
                bf[0] = b1[2]; bf[1] = b1[3];
                mma_f16(acc[3], a, bf);
            }
        }
    }
    float* stp = g_st + (size_t)bh * 2048;
    int grow = gseg + (lane >> 2);
#pragma unroll
    for (int ni = 0; ni < 4; ni++) {
        int dcol = ni * 8 + (lane & 3) * 2;
        atomicAdd(&stp[grow * 32 + dcol], acc[ni][0]);
        atomicAdd(&stp[grow * 32 + dcol + 1], acc[ni][1]);
        atomicAdd(&stp[(grow + 8) * 32 + dcol], acc[ni][2]);
        atomicAdd(&stp[(grow + 8) * 32 + dcol + 1], acc[ni][3]);
    }
    atomicAdd(&g_norm[bh * 64 + 2 * ng2], nacc.x);
    atomicAdd(&g_norm[bh * 64 + 2 * ng2 + 1], nacc.y);
}

// normalize st, q/k/v, 64x64 attention; write half2-packed ot (g-pairs)
__global__ void qkv_attn_kernel(const float* __restrict__ wq,
                                const float* __restrict__ wk,
                                const float* __restrict__ wv) {
    int bh = blockIdx.x;
    int tid = threadIdx.x;  // 256
    __shared__ float st_s[2048], q_s[2048], k_s[2048], s_s[4096];
    for (int i = tid; i < 2048; i += 256) {
        int g = i >> 5;
        st_s[i] = g_st[bh * 2048 + i] / (g_norm[bh * 64 + g] + 1e-5f);
    }
    __syncthreads();
    for (int i = tid; i < 2048; i += 256) {
        int g = i >> 5, d = i & 31;
        float aq = 0.f, ak = 0.f;
#pragma unroll
        for (int c = 0; c < 32; c++) {
            float s = st_s[g * 32 + c];
            aq += s * wq[c * 32 + d];
            ak += s * wk[c * 32 + d];
        }
        q_s[i] = aq;
        k_s[i] = ak;
    }
    __syncthreads();
    const float scale = 0.17677669529663687f;
    for (int i = tid; i < 4096; i += 256) {
        int g = i >> 6, j = i & 63;
        float a = 0.f;
#pragma unroll
        for (int d = 0; d < 32; d++) a += q_s[g * 32 + d] * k_s[j * 32 + d];
        s_s[i] = a * scale;
    }
    __syncthreads();
    if (tid < 64) {
        float m = -1e30f;
        for (int j = 0; j < 64; j++) m = fmaxf(m, s_s[tid * 64 + j]);
        float sum = 0.f;
        for (int j = 0; j < 64; j++) {
            float e = expf(s_s[tid * 64 + j] - m);
            s_s[tid * 64 + j] = e;
            sum += e;
        }
        float inv = 1.f / sum;
        for (int j = 0; j < 64; j++) s_s[tid * 64 + j] *= inv;
    }
    __syncthreads();
    for (int i = tid; i < 2048; i += 256) {
        int g = i >> 5, d = i & 31;
        float a = 0.f;
#pragma unroll
        for (int j = 0; j < 64; j++) a += s_s[g * 64 + j] * st_s[j * 32 + d];
        q_s[i] = a;
    }
    __syncthreads();
    for (int i = tid; i < 2048; i += 256) {
        int g = i >> 5, d = i & 31;
        float a = 0.f;
#pragma unroll
        for (int c = 0; c < 32; c++) a += q_s[g * 32 + c] * wv[c * 32 + d];
        k_s[i] = a;
    }
    __syncthreads();
    for (int i = tid; i < 1024; i += 256) {
        int gp = i >> 5, d = i & 31;
        g_otp[bh * 1024 + i] = packh(k_s[(2 * gp) * 32 + d], k_s[(2 * gp + 1) * 32 + d]);
    }
}

// ============ deslice via fp16 mma: outx[128n x 32d] = sw[128n x 64g] @ ot ===
__global__ __launch_bounds__(256, 2)
void deslice_mma_kernel() {
    __shared__ uint32_t As[128][36];
    __shared__ uint32_t Bp[32][33];
    int n0 = blockIdx.x * 128;
    int bh = blockIdx.y;
    int b = bh >> 3, h = bh & 7;
    int tid = threadIdx.x;
    int wid = tid >> 5, lane = tid & 31;
    int wm = wid * 16;
    int gid = lane >> 2, tig = lane & 3;

    const uint32_t* swp = (const uint32_t*)g_swh + ((size_t)bh * Nn + n0) * 32;
#pragma unroll
    for (int j = 0; j < 4; j++) {
        int s = tid + 256 * j;
        int r = s >> 3, c = (s & 7) * 4;
        *(uint4*)&As[r][c] = *(const uint4*)&swp[(size_t)r * 32 + c];
    }
#pragma unroll
    for (int j = 0; j < 4; j++) {
        int s = tid + 256 * j;
        Bp[s >> 5][s & 31] = g_otp[bh * 1024 + s];
    }
    __syncthreads();

    uint32_t smemA = (uint32_t)__cvta_generic_to_shared(&As[0][0]);
    int arow = wm + (lane & 7) + ((lane >> 3) & 1) * 8;
    uint32_t aBase = smemA + (uint32_t)((arow * 36 + ((lane >> 4) << 2)) * 4);

    float acc[4][4];
#pragma unroll
    for (int ni = 0; ni < 4; ni++)
#pragma unroll
        for (int q = 0; q < 4; q++) acc[ni][q] = 0.f;

#pragma unroll
    for (int ks = 0; ks < 4; ks++) {
        uint32_t a[4];
        ldsm4(a[0], a[1], a[2], a[3], aBase + ks * 32);
#pragma unroll
        for (int ni = 0; ni < 4; ni++) {
            uint32_t bfr[2];
            bfr[0] = Bp[ks * 8 + tig][ni * 8 + gid];
            bfr[1] = Bp[ks * 8 + tig + 4][ni * 8 + gid];
            mma_f16(acc[ni], a, bfr);
        }
    }
    int r = n0 + wm + gid;
#pragma unroll
    for (int ni = 0; ni < 4; ni++) {
        int dp = ni * 4 + tig;
        g_outxbf[((size_t)b * Nn + r) * 128 + h * 16 + dp] = packbf(acc[ni][0], acc[ni][1]);
        g_outxbf[((size_t)b * Nn + r + 8) * 128 + h * 16 + dp] = packbf(acc[ni][2], acc[ni][3]);
    }
}

// ---------------- driver ----------------
extern "C" void kernel_launch(void* const* d_in, const int* in_sizes, int n_in,
                              void* d_out, int out_size) {
    const float* fx_in  = (const float*)d_in[0];
    const float* ln1_w  = (const float*)d_in[1];
    const float* ln1_b  = (const float*)d_in[2];
    const float* convx_w  = (const float*)d_in[3];
    const float* convx_b  = (const float*)d_in[4];
    const float* convfx_w = (const float*)d_in[5];
    const float* convfx_b = (const float*)d_in[6];
    const float* slice_w  = (const float*)d_in[7];
    const float* slice_b  = (const float*)d_in[8];
    const float* temperature = (const float*)d_in[9];
    const float* wq = (const float*)d_in[10];
    const float* wk = (const float*)d_in[11];
    const float* wv = (const float*)d_in[12];
    const float* wo = (const float*)d_in[13];
    const float* bo = (const float*)d_in[14];
    const float* ln2_w = (const float*)d_in[15];
    const float* ln2_b = (const float*)d_in[16];
    const float* w1 = (const float*)d_in[17];
    const float* b1 = (const float*)d_in[18];
    const float* w2 = (const float*)d_in[19];
    const float* b2 = (const float*)d_in[20];
    const float* ln3_w = (const float*)d_in[21];
    const float* ln3_b = (const float*)d_in[22];
    const float* w_out = (const float*)d_in[23];
    const float* b_out = (const float*)d_in[24];

    float* p_fx;
    uint32_t *p_lnbf, *p_xmidh, *p_fxmidh, *p_outxbf, *p_hidbf, *p_wpk;
    cudaGetSymbolAddress((void**)&p_fx, g_fx);
    cudaGetSymbolAddress((void**)&p_lnbf, g_lnbf);
    cudaGetSymbolAddress((void**)&p_xmidh, g_xmidh);
    cudaGetSymbolAddress((void**)&p_fxmidh, g_fxmidh);
    cudaGetSymbolAddress((void**)&p_outxbf, g_outxbf);
    cudaGetSymbolAddress((void**)&p_hidbf, g_hidbf);
    cudaGetSymbolAddress((void**)&p_wpk, g_wpk);

    cudaFuncSetAttribute(conv_bf16_kernel, cudaFuncAttributeMaxDynamicSharedMemorySize,
                         HA_SMEM);

    pack_kernel<<<2048, 256>>>(convx_w, p_wpk + WPK_CONVX, 1152, 256, Lnum,
                               (size_t)2304 * 256, WPK_LAYER);
    pack_kernel<<<2048, 256>>>(convfx_w, p_wpk + WPK_CONVFX, 1152, 256, Lnum,
                               (size_t)2304 * 256, WPK_LAYER);
    pack_kernel<<<256, 256>>>(wo, p_wpk + WPK_WO, 128, 256, Lnum,
                              (size_t)256 * 256, WPK_LAYER);
    pack_kernel<<<1024, 256>>>(w1, p_wpk + WPK_W1, 128, 1024, Lnum,
                               (size_t)256 * 1024, WPK_LAYER);
    pack_kernel<<<1024, 256>>>(w2, p_wpk + WPK_W2, 512, 256, Lnum,
                               (size_t)1024 * 256, WPK_LAYER);

    copy_in_kernel<<<ROWS * Cc / 256, 256>>>(fx_in);

    for (int i = 0; i < Lnum; i++) {
        const uint32_t* wl = p_wpk + (size_t)i * WPK_LAYER;
        ln8_kernel<<<ROWS / 8, 256>>>(p_fx, p_lnbf, ln1_w + i * Cc, ln1_b + i * Cc);
        dim3 cg(ROWS / 128, 2);
        conv_bf16_kernel<<<cg, 256, HA_SMEM>>>(p_lnbf, wl + WPK_CONVX, convx_b + i * INNERc,
                                               p_xmidh);
        conv_bf16_kernel<<<cg, 256, HA_SMEM>>>(p_lnbf, wl + WPK_CONVFX, convfx_b + i * INNERc,
                                               p_fxmidh);
        slice_softmax_kernel<<<ROWS, 512>>>(p_xmidh, slice_w + i * DHd * Gg,
                                            slice_b + i * Gg, temperature + i * HEADS);
        zero_stats_kernel<<<(Bsz * HEADS * Gg * DHd + 255) / 256, 256>>>();
        st_mma_kernel<<<dim3(Bsz * HEADS, 16), 256>>>();
        qkv_attn_kernel<<<Bsz * HEADS, 256>>>(wq + i * DHd * DHd, wk + i * DHd * DHd,
                                              wv + i * DHd * DHd);
        deslice_mma_kernel<<<dim3(Nn / 128, Bsz * HEADS), 256>>>();
        gemm_bf16_kernel<false, true, false><<<dim3(ROWS / 128, 2), 256>>>(
            p_outxbf, wl + WPK_WO, bo + i * Cc, p_fx, p_fx, nullptr, 128, Cc);
        ln8_kernel<<<ROWS / 8, 256>>>(p_fx, p_lnbf, ln2_w + i * Cc, ln2_b + i * Cc);
        gemm_bf16_kernel<true, false, true><<<dim3(ROWS / 128, HIDc / 128), 256>>>(
            p_lnbf, wl + WPK_W1, b1 + i * HIDc, nullptr, nullptr, p_hidbf, 128, HIDc);
        gemm_bf16_kernel<false, true, false><<<dim3(ROWS / 128, 2), 256>>>(
            p_hidbf, wl + WPK_W2, b2 + i * Cc, p_fx, p_fx, nullptr, 512, Cc);
    }

    ln_head_kernel<<<ROWS / 8, 256>>>(p_fx, ln3_w, ln3_b, w_out, b_out, (float*)d_out);
}